// round 3
// baseline (speedup 1.0000x reference)
#include <cuda_runtime.h>
#include <math.h>

#define NB 2
#define NC 512
#define NH 64
#define NW 64
#define NHW 4096
#define NA 36864      // H*W*9 anchors
#define KSZ 4608      // 512*9
#define PRE 2000
#define POST 300

// ---------------- scratch (device globals; no allocation) ----------------
__device__ float  g_wT[(size_t)KSZ * 512];          // transposed 3x3 weights [k][o]
__device__ float  g_shr[(size_t)NB * NC * NHW];     // shared conv output (NCHW)
__device__ float  g_act[(size_t)NB * NHW * 54];     // cls(18)+reg(36) logits, (b,pos,54)
__device__ float  g_anc[NA * 4];
__device__ int    g_val[NA];
__device__ int    g_K;
__device__ float4 g_box[NB * NA];
__device__ float  g_sco[NB * NA];
__device__ float4 g_tb[NB * PRE];
__device__ float  g_ts[NB * PRE];

// ---------------- helpers ----------------
__device__ __forceinline__ unsigned fkey(float f) {
    unsigned u = __float_as_uint(f);
    return (u & 0x80000000u) ? ~u : (u | 0x80000000u);
}

// ---------------- 0: transpose 3x3 weights to [k][o] ----------------
__global__ void k_wt(const float* __restrict__ w) {
    int i = blockIdx.x * blockDim.x + threadIdx.x;
    if (i < 512 * KSZ) {
        int o = i / KSZ, k = i - o * KSZ;
        g_wT[(size_t)k * 512 + o] = w[i];
    }
}

// ---------------- 1: anchors + valid compaction (single block) ----------------
__global__ void k_anchors() {
    __shared__ float sbase[9][4];
    __shared__ int s_scan[1024];
    __shared__ int s_carry;
    int tid = threadIdx.x;
    if (tid == 0) {
        double ratios[3] = {0.5, 1.0, 2.0};
        double scales[3] = {8.0, 16.0, 32.0};
        int k = 0;
        for (int ri = 0; ri < 3; ri++)
            for (int si = 0; si < 3; si++) {
                double h = 16.0 * scales[si] * sqrt(ratios[ri]);
                double w = 16.0 * scales[si] * sqrt(1.0 / ratios[ri]);
                sbase[k][0] = (float)(8.0 - h / 2.0);
                sbase[k][1] = (float)(8.0 - w / 2.0);
                sbase[k][2] = (float)(8.0 + h / 2.0);
                sbase[k][3] = (float)(8.0 + w / 2.0);
                k++;
            }
        s_carry = 0;
    }
    __syncthreads();
    for (int c0 = 0; c0 < NA; c0 += 1024) {
        int a = c0 + tid;
        int pos = a / 9, j = a - pos * 9;
        int gy = pos >> 6, gx = pos & 63;
        float y1 = gy * 16.f + sbase[j][0];
        float x1 = gx * 16.f + sbase[j][1];
        float y2 = gy * 16.f + sbase[j][2];
        float x2 = gx * 16.f + sbase[j][3];
        g_anc[a * 4 + 0] = y1; g_anc[a * 4 + 1] = x1;
        g_anc[a * 4 + 2] = y2; g_anc[a * 4 + 3] = x2;
        int v = (y1 >= 0.f && x1 >= 0.f && y2 <= 1024.f && x2 <= 1024.f) ? 1 : 0;
        s_scan[tid] = v;
        __syncthreads();
        for (int off = 1; off < 1024; off <<= 1) {
            int t = (tid >= off) ? s_scan[tid - off] : 0;
            __syncthreads();
            s_scan[tid] += t;
            __syncthreads();
        }
        if (v) g_val[s_carry + s_scan[tid] - 1] = a;
        __syncthreads();
        if (tid == 0) s_carry += s_scan[1023];
        __syncthreads();
    }
    if (tid == 0) g_K = s_carry;
}

// ---------------- 2: 3x3 conv 512->512 SAME + bias + relu (fp32 tiled GEMM) ---
// block: Mtile = one (b,y) row of 64 x-positions, Ntile = 64 out channels.
__global__ void k_conv1(const float* __restrict__ feat, const float* __restrict__ bias) {
    int mt = blockIdx.x;         // 0..127 -> b,y
    int nt = blockIdx.y;         // 0..7
    int b = mt >> 6, y = mt & 63;
    int n0 = nt * 64;
    __shared__ float As[8][64];
    __shared__ float Bs[8][64];
    float acc[4][4] = {};
    int tid = threadIdx.x;
    int tx = tid & 15, to = tid >> 4;
    const float* fb = feat + (size_t)b * NC * NHW;
    for (int k0 = 0; k0 < KSZ; k0 += 8) {
#pragma unroll
        for (int s = 0; s < 2; ++s) {
            int idx = tid + s * 256;
            int kk = idx >> 6, x = idx & 63;
            int k = k0 + kk;
            int c = k / 9, r = k - c * 9;
            int dy = r / 3, dx = r - dy * 3;
            int yy = y + dy - 1, xx = x + dx - 1;
            float v = 0.f;
            if (yy >= 0 && yy < 64 && xx >= 0 && xx < 64)
                v = fb[((size_t)c * NH + yy) * NW + xx];
            As[kk][x] = v;
            Bs[kk][x] = g_wT[(size_t)k * 512 + n0 + x];
        }
        __syncthreads();
#pragma unroll
        for (int kk = 0; kk < 8; ++kk) {
            float4 av = ((const float4*)&As[kk][0])[tx];
            float4 bv = ((const float4*)&Bs[kk][0])[to];
            float a[4] = {av.x, av.y, av.z, av.w};
            float bb[4] = {bv.x, bv.y, bv.z, bv.w};
#pragma unroll
            for (int i = 0; i < 4; ++i)
#pragma unroll
                for (int j = 0; j < 4; ++j)
                    acc[i][j] += a[i] * bb[j];
        }
        __syncthreads();
    }
#pragma unroll
    for (int j = 0; j < 4; ++j) {
        int o = n0 + to * 4 + j;
        float bo = bias[o];
#pragma unroll
        for (int i = 0; i < 4; ++i) {
            int x = tx * 4 + i;
            float v = acc[i][j] + bo;
            g_shr[(((size_t)b * NC + o) * NH + y) * NW + x] = fmaxf(v, 0.f);
        }
    }
}

// ---------------- 3: 1x1 convs (cls 18 + reg 36 = 54 outputs) ----------------
__global__ void k_conv2(const float* __restrict__ cls_w, const float* __restrict__ cls_b,
                        const float* __restrict__ reg_w, const float* __restrict__ reg_b) {
    int blk = blockIdx.x;        // (b,y)
    int b = blk >> 6, y = blk & 63;
    __shared__ float sin_[64][64];
    __shared__ float sw[64][56];
    int tid = threadIdx.x;       // 512 threads
    int x = tid & 63, og = tid >> 6;
    float acc[7] = {};
    for (int c0 = 0; c0 < 512; c0 += 64) {
        for (int idx = tid; idx < 4096; idx += 512) {
            int c = idx >> 6, xx = idx & 63;
            sin_[c][xx] = g_shr[(((size_t)b * NC + c0 + c) * NH + y) * NW + xx];
        }
        for (int idx = tid; idx < 64 * 56; idx += 512) {
            int c = idx / 56, o = idx - c * 56;
            float v = 0.f;
            if (o < 18) v = cls_w[(size_t)o * 512 + c0 + c];
            else if (o < 54) v = reg_w[(size_t)(o - 18) * 512 + c0 + c];
            sw[c][o] = v;
        }
        __syncthreads();
#pragma unroll 8
        for (int c = 0; c < 64; ++c) {
            float a = sin_[c][x];
#pragma unroll
            for (int i = 0; i < 7; ++i) acc[i] += a * sw[c][og + 8 * i];
        }
        __syncthreads();
    }
    for (int i = 0; i < 7; ++i) {
        int o = og + 8 * i;
        if (o < 54) {
            float bs = (o < 18) ? cls_b[o] : reg_b[o - 18];
            g_act[((size_t)b * NHW + y * 64 + x) * 54 + o] = acc[i] + bs;
        }
    }
}

// ---------------- 4: gather + softmax + decode + clip + minsize --------------
__global__ void k_decode(float* __restrict__ out) {
    int K = g_K;
    int t = blockIdx.x * blockDim.x + threadIdx.x;
    if (t >= 2 * K) return;
    int b = t / K, k = t - b * K;
    int a = g_val[k];
    int pos = a / 9, j = a - pos * 9;
    const float* ab = g_act + ((size_t)b * NHW + pos) * 54;
    float l0 = ab[2 * j], l1 = ab[2 * j + 1];
    float m = fmaxf(l0, l1);
    float e0 = expf(__fadd_rn(l0, -m)), e1 = expf(__fadd_rn(l1, -m));
    float s = __fadd_rn(e0, e1);
    float p0 = __fdiv_rn(e0, s), p1 = __fdiv_rn(e1, s);
    out[(size_t)(b * K + k) * 2 + 0] = p0;
    out[(size_t)(b * K + k) * 2 + 1] = p1;
    float d0 = ab[18 + 4 * j], d1 = ab[19 + 4 * j], d2 = ab[20 + 4 * j], d3 = ab[21 + 4 * j];
    size_t ro = (size_t)4 * K;
    out[ro + (size_t)(b * K + k) * 4 + 0] = d0;
    out[ro + (size_t)(b * K + k) * 4 + 1] = d1;
    out[ro + (size_t)(b * K + k) * 4 + 2] = d2;
    out[ro + (size_t)(b * K + k) * 4 + 3] = d3;
    float ay1 = g_anc[a * 4 + 0], ax1 = g_anc[a * 4 + 1];
    float ay2 = g_anc[a * 4 + 2], ax2 = g_anc[a * 4 + 3];
    float h  = __fadd_rn(ay2, -ay1);
    float w  = __fadd_rn(ax2, -ax1);
    float cy = __fadd_rn(ay1, __fmul_rn(0.5f, h));
    float cx = __fadd_rn(ax1, __fmul_rn(0.5f, w));
    float ncy = __fadd_rn(__fmul_rn(d0, h), cy);
    float ncx = __fadd_rn(__fmul_rn(d1, w), cx);
    float nh = __fmul_rn(h, expf(d2));
    float nw = __fmul_rn(w, expf(d3));
    float y1 = __fadd_rn(ncy, -__fmul_rn(0.5f, nh));
    float x1 = __fadd_rn(ncx, -__fmul_rn(0.5f, nw));
    float y2 = __fadd_rn(ncy,  __fmul_rn(0.5f, nh));
    float x2 = __fadd_rn(ncx,  __fmul_rn(0.5f, nw));
    y1 = fminf(fmaxf(y1, 0.f), 1024.f);
    x1 = fminf(fmaxf(x1, 0.f), 1024.f);
    y2 = fminf(fmaxf(y2, 0.f), 1024.f);
    x2 = fminf(fmaxf(x2, 0.f), 1024.f);
    float hs = __fadd_rn(y2, -y1), ws = __fadd_rn(x2, -x1);
    float score = (hs >= 16.f && ws >= 16.f) ? p1 : -INFINITY;
    g_box[(size_t)b * NA + k] = make_float4(y1, x1, y2, x2);
    g_sco[(size_t)b * NA + k] = score;
}

// ---------------- 5: write all anchors to output -----------------------------
__global__ void k_wanchors(float* __restrict__ out) {
    size_t off = (size_t)g_K * 12 + 3000;
    for (int i = blockIdx.x * blockDim.x + threadIdx.x; i < NA * 4;
         i += gridDim.x * blockDim.x)
        out[off + i] = g_anc[i];
}

// ---------------- bitonic sorts (shared, n=2048, 1024 threads) ---------------
__device__ void bitonic2048_u64(unsigned long long* buf, int tid) {
    for (int k = 2; k <= 2048; k <<= 1)
        for (int j = k >> 1; j > 0; j >>= 1) {
            for (int i = tid; i < 2048; i += 1024) {
                int ixj = i ^ j;
                if (ixj > i) {
                    unsigned long long a = buf[i], c = buf[ixj];
                    bool up = ((i & k) == 0);
                    if ((a > c) == up) { buf[i] = c; buf[ixj] = a; }
                }
            }
            __syncthreads();
        }
}
__device__ void bitonic2048_u32(unsigned* buf, int tid) {
    for (int k = 2; k <= 2048; k <<= 1)
        for (int j = k >> 1; j > 0; j >>= 1) {
            for (int i = tid; i < 2048; i += 1024) {
                int ixj = i ^ j;
                if (ixj > i) {
                    unsigned a = buf[i], c = buf[ixj];
                    bool up = ((i & k) == 0);
                    if ((a > c) == up) { buf[i] = c; buf[ixj] = a; }
                }
            }
            __syncthreads();
        }
}

// ---------------- 6: exact top-2000 (radix select + sort), per batch ---------
__global__ void k_topk() {
    int b = blockIdx.x;
    int tid = threadIdx.x;                 // 1024
    int N = g_K;
    const float* sc = g_sco + (size_t)b * NA;
    __shared__ unsigned hist[256];
    __shared__ unsigned long long sbuf[2048];
    __shared__ unsigned idxbuf[2048];
    __shared__ int s_bin, s_need, s_cgt, s_ceq;

    unsigned prefix = 0;
    int need = PRE;
    for (int shift = 24; shift >= 0; shift -= 8) {
        if (tid < 256) hist[tid] = 0;
        __syncthreads();
        unsigned himask = (shift == 24) ? 0u : (0xFFFFFFFFu << (shift + 8));
        for (int i = tid; i < N; i += 1024) {
            unsigned key = fkey(sc[i]);
            if ((key & himask) == prefix) atomicAdd(&hist[(key >> shift) & 255u], 1u);
        }
        __syncthreads();
        if (tid == 0) {
            int nd = need, bin = 255;
            for (; bin >= 0; --bin) {
                int c = (int)hist[bin];
                if (nd <= c) break;
                nd -= c;
            }
            s_bin = bin; s_need = nd;
        }
        __syncthreads();
        prefix |= ((unsigned)s_bin) << shift;
        need = s_need;
        __syncthreads();
    }
    unsigned T = prefix;   // exact 2000th-largest key; need = count to take among ==T

    if (tid == 0) { s_cgt = 0; s_ceq = 0; }
    for (int i = tid; i < 2048; i += 1024) { sbuf[i] = ~0ULL; idxbuf[i] = 0xFFFFFFFFu; }
    __syncthreads();
    for (int i = tid; i < N; i += 1024) {
        unsigned key = fkey(sc[i]);
        if (key > T) {
            int p = atomicAdd(&s_cgt, 1);
            sbuf[p] = (((unsigned long long)(~key)) << 32) | (unsigned)i;
        } else if (key == T) {
            int p = atomicAdd(&s_ceq, 1);
            if (p < 2048) idxbuf[p] = (unsigned)i;
        }
    }
    __syncthreads();
    bitonic2048_u32(idxbuf, tid);          // smallest indices first among ties
    int cgt = s_cgt;
    for (int t2 = tid; t2 < need; t2 += 1024)
        sbuf[cgt + t2] = (((unsigned long long)(~T)) << 32) | idxbuf[t2];
    __syncthreads();
    bitonic2048_u64(sbuf, tid);            // (score desc, idx asc)
    for (int t2 = tid; t2 < PRE; t2 += 1024) {
        unsigned idx = (unsigned)(sbuf[t2] & 0xFFFFFFFFu);
        g_tb[b * PRE + t2] = g_box[(size_t)b * NA + idx];
        g_ts[b * PRE + t2] = sc[idx];
    }
}

// ---------------- 7: greedy NMS over sorted candidates, per batch ------------
__global__ void k_nms(float* __restrict__ out) {
    int b = blockIdx.x;
    int tid = threadIdx.x;                 // 256
    int K = g_K;
    size_t OFF_ROI = (size_t)K * 12;
    size_t OFF_ID  = OFF_ROI + 2400;
    __shared__ float by1[PRE], bx1[PRE], by2[PRE], bx2[PRE], bar[PRE];
    __shared__ int alive[PRE];
    __shared__ int s_cur, s_kept, s_p;
    for (int i = tid; i < PRE; i += blockDim.x) {
        float4 bb = g_tb[b * PRE + i];
        by1[i] = bb.x; bx1[i] = bb.y; by2[i] = bb.z; bx2[i] = bb.w;
        bar[i] = __fmul_rn(__fadd_rn(bb.z, -bb.x), __fadd_rn(bb.w, -bb.y));
        alive[i] = (g_ts[b * PRE + i] > -INFINITY) ? 1 : 0;
    }
    if (tid == 0) { s_kept = 0; s_p = 0; }
    __syncthreads();
    while (true) {
        if (tid == 0) {
            int p = s_p;
            while (p < PRE && !alive[p]) p++;
            if (p < PRE && s_kept < POST) {
                alive[p] = 0;
                int kk = s_kept++;
                float* ro = out + OFF_ROI + ((size_t)b * POST + kk) * 4;
                ro[0] = by1[p]; ro[1] = bx1[p]; ro[2] = by2[p]; ro[3] = bx2[p];
                s_cur = p;
                s_p = p + 1;
            } else s_cur = -1;
        }
        __syncthreads();
        int cur = s_cur;
        if (cur < 0) break;
        float py1 = by1[cur], px1 = bx1[cur], py2 = by2[cur], px2 = bx2[cur], pa = bar[cur];
        for (int j = cur + 1 + tid; j < PRE; j += blockDim.x) {
            if (!alive[j]) continue;
            float yy1 = fmaxf(py1, by1[j]);
            float xx1 = fmaxf(px1, bx1[j]);
            float yy2 = fminf(py2, by2[j]);
            float xx2 = fminf(px2, bx2[j]);
            float inter = __fmul_rn(fmaxf(__fadd_rn(yy2, -yy1), 0.f),
                                    fmaxf(__fadd_rn(xx2, -xx1), 0.f));
            float denom = __fadd_rn(__fadd_rn(__fadd_rn(pa, bar[j]), -inter), 1e-9f);
            if (__fdiv_rn(inter, denom) > 0.7f) alive[j] = 0;
        }
        __syncthreads();
    }
    for (int i = tid; i < POST; i += blockDim.x) {
        if (i >= s_kept) {
            float* ro = out + OFF_ROI + ((size_t)b * POST + i) * 4;
            ro[0] = 0.f; ro[1] = 0.f; ro[2] = 0.f; ro[3] = 0.f;
        }
        out[OFF_ID + b * POST + i] = (float)b;
    }
}

// ---------------- launch ----------------
extern "C" void kernel_launch(void* const* d_in, const int* in_sizes, int n_in,
                              void* d_out, int out_size) {
    const float* feat    = (const float*)d_in[0];
    const float* share_w = (const float*)d_in[1];
    const float* share_b = (const float*)d_in[2];
    const float* cls_w   = (const float*)d_in[3];
    const float* cls_b   = (const float*)d_in[4];
    const float* reg_w   = (const float*)d_in[5];
    const float* reg_b   = (const float*)d_in[6];
    float* out = (float*)d_out;

    k_wt<<<(512 * KSZ + 255) / 256, 256>>>(share_w);
    k_anchors<<<1, 1024>>>();
    k_conv1<<<dim3(128, 8), 256>>>(feat, share_b);
    k_conv2<<<128, 512>>>(cls_w, cls_b, reg_w, reg_b);
    k_decode<<<(2 * NA + 255) / 256, 256>>>(out);
    k_wanchors<<<576, 256>>>(out);
    k_topk<<<2, 1024>>>();
    k_nms<<<2, 256>>>(out);
}

// round 5
// speedup vs baseline: 1.3017x; 1.3017x over previous
#include <cuda_runtime.h>
#include <math.h>

#define NB 2
#define NC 512
#define NH 64
#define NW 64
#define NHW 4096
#define NA 36864      // H*W*9 anchors
#define KSZ 4608      // 512*9
#define PRE 2000
#define POST 300

// halo'd split-feat planes: [3][b][c][66][66]
#define FHW 66
#define FPLANE (NB * NC * FHW * FHW)

// ---------------- scratch (device globals; no allocation) ----------------
__device__ __align__(16) unsigned short g_ws[3][(size_t)512 * KSZ];   // weight planes [o][k]
__device__ __align__(16) unsigned short g_fs[3][(size_t)FPLANE];      // feat planes, halo
__device__ float  g_shr[(size_t)NB * NC * NHW];     // shared conv output (NCHW)
__device__ float  g_act[(size_t)NB * NHW * 54];     // cls(18)+reg(36) logits, (b,pos,54)
__device__ float  g_anc[NA * 4];
__device__ int    g_val[NA];
__device__ int    g_K;
__device__ float4 g_box[NB * NA];
__device__ float  g_sco[NB * NA];
__device__ float4 g_tb[NB * PRE];
__device__ float  g_ts[NB * PRE];

// ---------------- helpers ----------------
__device__ __forceinline__ unsigned fkey(float f) {
    unsigned u = __float_as_uint(f);
    return (u & 0x80000000u) ? ~u : (u | 0x80000000u);
}
__device__ __forceinline__ unsigned smem_u32(const void* p) {
    unsigned a;
    asm("{ .reg .u64 t; cvta.to.shared.u64 t, %1; cvt.u32.u64 %0, t; }" : "=r"(a) : "l"(p));
    return a;
}
// round-to-nearest-even fp32 -> bf16 (bits kept in high half)
__device__ __forceinline__ unsigned bf16hi(float v) {
    unsigned u = __float_as_uint(v);
    return (u + 0x7FFFu + ((u >> 16) & 1u)) & 0xFFFF0000u;
}
__device__ __forceinline__ void split3(float v, unsigned short& h, unsigned short& m,
                                       unsigned short& l) {
    unsigned rh = bf16hi(v);
    float r1 = v - __uint_as_float(rh);
    unsigned rm = bf16hi(r1);
    float r2 = r1 - __uint_as_float(rm);
    unsigned rl = bf16hi(r2);
    h = (unsigned short)(rh >> 16);
    m = (unsigned short)(rm >> 16);
    l = (unsigned short)(rl >> 16);
}
#define STS128(a0, a1, a2, a3, addr) \
    asm volatile("st.shared.v4.b32 [%0], {%1, %2, %3, %4};" \
                 :: "r"(addr), "r"(a0), "r"(a1), "r"(a2), "r"(a3) : "memory")
__device__ __forceinline__ void ldmx4(unsigned* r, unsigned addr) {
    asm volatile("ldmatrix.sync.aligned.m8n8.x4.shared.b16 {%0,%1,%2,%3}, [%4];"
                 : "=r"(r[0]), "=r"(r[1]), "=r"(r[2]), "=r"(r[3]) : "r"(addr));
}
__device__ __forceinline__ void ldmx4t(unsigned* r, unsigned addr) {
    asm volatile("ldmatrix.sync.aligned.m8n8.x4.trans.shared.b16 {%0,%1,%2,%3}, [%4];"
                 : "=r"(r[0]), "=r"(r[1]), "=r"(r[2]), "=r"(r[3]) : "r"(addr));
}
__device__ __forceinline__ void mma16816(float* c, const unsigned* a, unsigned b0,
                                         unsigned b1) {
    asm volatile(
        "mma.sync.aligned.m16n8k16.row.col.f32.bf16.bf16.f32 "
        "{%0,%1,%2,%3},{%4,%5,%6,%7},{%8,%9},{%0,%1,%2,%3};"
        : "+f"(c[0]), "+f"(c[1]), "+f"(c[2]), "+f"(c[3])
        : "r"(a[0]), "r"(a[1]), "r"(a[2]), "r"(a[3]), "r"(b0), "r"(b1));
}

// ---------------- 0a: split weights into 3 bf16 planes [o][k] ----------------
__global__ void k_wsplit(const float* __restrict__ w) {
    int i = blockIdx.x * blockDim.x + threadIdx.x;
    if (i < 512 * KSZ) {
        unsigned short h, m, l;
        split3(w[i], h, m, l);
        g_ws[0][i] = h; g_ws[1][i] = m; g_ws[2][i] = l;
    }
}

// ---------------- 0b: split feat into 3 bf16 planes with 1px zero halo -------
__global__ void k_fsplit(const float* __restrict__ feat) {
    int i = blockIdx.x * blockDim.x + threadIdx.x;
    if (i >= FPLANE) return;
    int xx = i % FHW;
    int t = i / FHW;
    int yy = t % FHW;
    int bc = t / FHW;                  // 0..1023 = b*512+c
    float v = 0.f;
    if (xx >= 1 && xx <= 64 && yy >= 1 && yy <= 64)
        v = feat[(size_t)bc * NHW + (yy - 1) * 64 + (xx - 1)];
    unsigned short h, m, l;
    split3(v, h, m, l);
    g_fs[0][i] = h; g_fs[1][i] = m; g_fs[2][i] = l;
}

// ---------------- 1: anchors + valid compaction (single block) ----------------
__global__ void k_anchors() {
    __shared__ float sbase[9][4];
    __shared__ int s_scan[1024];
    __shared__ int s_carry;
    int tid = threadIdx.x;
    if (tid == 0) {
        double ratios[3] = {0.5, 1.0, 2.0};
        double scales[3] = {8.0, 16.0, 32.0};
        int k = 0;
        for (int ri = 0; ri < 3; ri++)
            for (int si = 0; si < 3; si++) {
                double h = 16.0 * scales[si] * sqrt(ratios[ri]);
                double w = 16.0 * scales[si] * sqrt(1.0 / ratios[ri]);
                sbase[k][0] = (float)(8.0 - h / 2.0);
                sbase[k][1] = (float)(8.0 - w / 2.0);
                sbase[k][2] = (float)(8.0 + h / 2.0);
                sbase[k][3] = (float)(8.0 + w / 2.0);
                k++;
            }
        s_carry = 0;
    }
    __syncthreads();
    for (int c0 = 0; c0 < NA; c0 += 1024) {
        int a = c0 + tid;
        int pos = a / 9, j = a - pos * 9;
        int gy = pos >> 6, gx = pos & 63;
        float y1 = gy * 16.f + sbase[j][0];
        float x1 = gx * 16.f + sbase[j][1];
        float y2 = gy * 16.f + sbase[j][2];
        float x2 = gx * 16.f + sbase[j][3];
        g_anc[a * 4 + 0] = y1; g_anc[a * 4 + 1] = x1;
        g_anc[a * 4 + 2] = y2; g_anc[a * 4 + 3] = x2;
        int v = (y1 >= 0.f && x1 >= 0.f && y2 <= 1024.f && x2 <= 1024.f) ? 1 : 0;
        s_scan[tid] = v;
        __syncthreads();
        for (int off = 1; off < 1024; off <<= 1) {
            int t = (tid >= off) ? s_scan[tid - off] : 0;
            __syncthreads();
            s_scan[tid] += t;
            __syncthreads();
        }
        if (v) g_val[s_carry + s_scan[tid] - 1] = a;
        __syncthreads();
        if (tid == 0) s_carry += s_scan[1023];
        __syncthreads();
    }
    if (tid == 0) g_K = s_carry;
}

// ---- 2: 3x3 conv 512->512 SAME + bias + relu (mma.sync bf16 3-way split) ----
// GEMM C[8192][512] = im2col(feat)[8192][4608] x W^T; CTA 128x64, kstep 32.
#define ASTRIDE 136   // halves per A k-row (272B, 16B aligned, conflict-free)
#define BSTRIDE 40    // halves per B n-row (80B)

__global__ __launch_bounds__(256, 2) void k_conv1mma(const float* __restrict__ bias) {
    __shared__ __align__(16) unsigned short sA[3][32 * ASTRIDE];
    __shared__ __align__(16) unsigned short sB[3][64 * BSTRIDE];
    const int tid = threadIdx.x;
    const int wid = tid >> 5, lane = tid & 31;
    const int wm = wid & 3, wn = wid >> 2;
    const int m0 = blockIdx.x * 128;
    const int n0 = blockIdx.y * 64;
    const int b = m0 >> 12;
    const int y0 = (m0 >> 6) & 63;

    float acc[2][4][4] = {};
    const unsigned sbA = smem_u32(&sA[0][0]);
    const unsigned sbB = smem_u32(&sB[0][0]);

    // per-thread ldmatrix address components (constant over chunks)
    const int a_krow = (lane & 7) + (((lane >> 4) & 1) << 3);     // + k16
    const int a_moff = ((lane >> 3) & 1) << 3;                    // + wm*32 + i*16
    const int b_nrow = wn * 32 + (((lane >> 4) & 1) << 3) + (lane & 7);  // + jj*16
    const int b_koff = ((lane >> 3) & 1) << 3;                    // + k16

#pragma unroll 1
    for (int ch = 0; ch < KSZ / 32; ++ch) {
        const int k0 = ch * 32;
        __syncthreads();
        // ---- stage A: [k][m], 3 planes ----
#pragma unroll
        for (int it = 0; it < 6; ++it) {
            int t = tid + (it << 8);
            int p = t >> 9;
            int rem = t & 511;
            int kk = rem >> 4, oct = rem & 15;
            int k = k0 + kk;
            int c = k / 9;
            int r = k - c * 9;
            int dy = r / 3, dx = r - dy * 3;
            int y = y0 + (oct >> 3);
            int x0 = (oct & 7) << 3;
            const unsigned short* s =
                &g_fs[p][((size_t)((b * NC + c) * FHW + (y + dy))) * FHW + (x0 + dx)];
            unsigned v0 = (unsigned)s[0] | ((unsigned)s[1] << 16);
            unsigned v1 = (unsigned)s[2] | ((unsigned)s[3] << 16);
            unsigned v2 = (unsigned)s[4] | ((unsigned)s[5] << 16);
            unsigned v3 = (unsigned)s[6] | ((unsigned)s[7] << 16);
            STS128(v0, v1, v2, v3, sbA + p * (32 * ASTRIDE * 2) + kk * (ASTRIDE * 2) + oct * 16);
        }
        // ---- stage B: [n][k], 3 planes ----
#pragma unroll
        for (int it = 0; it < 3; ++it) {
            int t = tid + (it << 8);
            int p = t >> 8;
            int rem = t & 255;
            int n = rem >> 2, kq = rem & 3;
            const uint4 v = *(const uint4*)&g_ws[p][(size_t)(n0 + n) * KSZ + k0 + (kq << 3)];
            STS128(v.x, v.y, v.z, v.w, sbB + p * (64 * BSTRIDE * 2) + n * (BSTRIDE * 2) + kq * 16);
        }
        __syncthreads();
        // ---- compute: 2 k16 steps, 6 products each ----
#pragma unroll
        for (int step = 0; step < 2; ++step) {
            const int k16 = step << 4;
            unsigned af[3][2][4], bf[3][2][4];
#pragma unroll
            for (int p = 0; p < 3; ++p) {
#pragma unroll
                for (int i = 0; i < 2; ++i)
                    ldmx4t(af[p][i], sbA + p * (32 * ASTRIDE * 2) +
                                     (k16 + a_krow) * (ASTRIDE * 2) +
                                     (wm * 32 + i * 16 + a_moff) * 2);
#pragma unroll
                for (int jj = 0; jj < 2; ++jj)
                    ldmx4(bf[p][jj], sbB + p * (64 * BSTRIDE * 2) +
                                     (b_nrow + jj * 16) * (BSTRIDE * 2) +
                                     (k16 + b_koff) * 2);
            }
            const int pa[6] = {0, 0, 1, 0, 1, 2};
            const int pb[6] = {0, 1, 0, 2, 1, 0};
#pragma unroll
            for (int q = 0; q < 6; ++q)
#pragma unroll
                for (int i = 0; i < 2; ++i)
#pragma unroll
                    for (int j = 0; j < 4; ++j)
                        mma16816(acc[i][j], af[pa[q]][i],
                                 bf[pb[q]][j >> 1][(j & 1) * 2],
                                 bf[pb[q]][j >> 1][(j & 1) * 2 + 1]);
        }
    }

    // ---- epilogue: bias + relu -> g_shr (NCHW) ----
    const int mb = m0 + wm * 32 + (lane >> 2);    // + i*16 (+8 for c2/c3)
    const int nb = n0 + wn * 32 + ((lane & 3) << 1);
#pragma unroll
    for (int i = 0; i < 2; ++i) {
#pragma unroll
        for (int j = 0; j < 4; ++j) {
            int o = nb + j * 8;
            float b0v = bias[o], b1v = bias[o + 1];
            int m_a = mb + i * 16;
            int m_b = m_a + 8;
            size_t pa_ = ((size_t)(b * NC + o) << 12);
            size_t pb_ = ((size_t)(b * NC + o + 1) << 12);
            g_shr[pa_ + (m_a & 4095)] = fmaxf(acc[i][j][0] + b0v, 0.f);
            g_shr[pb_ + (m_a & 4095)] = fmaxf(acc[i][j][1] + b1v, 0.f);
            g_shr[pa_ + (m_b & 4095)] = fmaxf(acc[i][j][2] + b0v, 0.f);
            g_shr[pb_ + (m_b & 4095)] = fmaxf(acc[i][j][3] + b1v, 0.f);
        }
    }
}

// ---------------- 3: 1x1 convs (cls 18 + reg 36 = 54 outputs) ----------------
__global__ void k_conv2(const float* __restrict__ cls_w, const float* __restrict__ cls_b,
                        const float* __restrict__ reg_w, const float* __restrict__ reg_b) {
    int blk = blockIdx.x;        // (b,y)
    int b = blk >> 6, y = blk & 63;
    __shared__ float sin_[64][64];
    __shared__ float sw[64][56];
    int tid = threadIdx.x;       // 512 threads
    int x = tid & 63, og = tid >> 6;
    float acc[7] = {};
    for (int c0 = 0; c0 < 512; c0 += 64) {
        for (int idx = tid; idx < 4096; idx += 512) {
            int c = idx >> 6, xx = idx & 63;
            sin_[c][xx] = g_shr[(((size_t)b * NC + c0 + c) * NH + y) * NW + xx];
        }
        for (int idx = tid; idx < 64 * 56; idx += 512) {
            int c = idx / 56, o = idx - c * 56;
            float v = 0.f;
            if (o < 18) v = cls_w[(size_t)o * 512 + c0 + c];
            else if (o < 54) v = reg_w[(size_t)(o - 18) * 512 + c0 + c];
            sw[c][o] = v;
        }
        __syncthreads();
#pragma unroll 8
        for (int c = 0; c < 64; ++c) {
            float a = sin_[c][x];
#pragma unroll
            for (int i = 0; i < 7; ++i) acc[i] += a * sw[c][og + 8 * i];
        }
        __syncthreads();
    }
    for (int i = 0; i < 7; ++i) {
        int o = og + 8 * i;
        if (o < 54) {
            float bs = (o < 18) ? cls_b[o] : reg_b[o - 18];
            g_act[((size_t)b * NHW + y * 64 + x) * 54 + o] = acc[i] + bs;
        }
    }
}

// ---------------- 4: gather + softmax + decode + clip + minsize --------------
__global__ void k_decode(float* __restrict__ out) {
    int K = g_K;
    int t = blockIdx.x * blockDim.x + threadIdx.x;
    if (t >= 2 * K) return;
    int b = t / K, k = t - b * K;
    int a = g_val[k];
    int pos = a / 9, j = a - pos * 9;
    const float* ab = g_act + ((size_t)b * NHW + pos) * 54;
    float l0 = ab[2 * j], l1 = ab[2 * j + 1];
    float m = fmaxf(l0, l1);
    float e0 = expf(__fadd_rn(l0, -m)), e1 = expf(__fadd_rn(l1, -m));
    float s = __fadd_rn(e0, e1);
    float p0 = __fdiv_rn(e0, s), p1 = __fdiv_rn(e1, s);
    out[(size_t)(b * K + k) * 2 + 0] = p0;
    out[(size_t)(b * K + k) * 2 + 1] = p1;
    float d0 = ab[18 + 4 * j], d1 = ab[19 + 4 * j], d2 = ab[20 + 4 * j], d3 = ab[21 + 4 * j];
    size_t ro = (size_t)4 * K;
    out[ro + (size_t)(b * K + k) * 4 + 0] = d0;
    out[ro + (size_t)(b * K + k) * 4 + 1] = d1;
    out[ro + (size_t)(b * K + k) * 4 + 2] = d2;
    out[ro + (size_t)(b * K + k) * 4 + 3] = d3;
    float ay1 = g_anc[a * 4 + 0], ax1 = g_anc[a * 4 + 1];
    float ay2 = g_anc[a * 4 + 2], ax2 = g_anc[a * 4 + 3];
    float h  = __fadd_rn(ay2, -ay1);
    float w  = __fadd_rn(ax2, -ax1);
    float cy = __fadd_rn(ay1, __fmul_rn(0.5f, h));
    float cx = __fadd_rn(ax1, __fmul_rn(0.5f, w));
    float ncy = __fadd_rn(__fmul_rn(d0, h), cy);
    float ncx = __fadd_rn(__fmul_rn(d1, w), cx);
    float nh = __fmul_rn(h, expf(d2));
    float nw = __fmul_rn(w, expf(d3));
    float y1 = __fadd_rn(ncy, -__fmul_rn(0.5f, nh));
    float x1 = __fadd_rn(ncx, -__fmul_rn(0.5f, nw));
    float y2 = __fadd_rn(ncy,  __fmul_rn(0.5f, nh));
    float x2 = __fadd_rn(ncx,  __fmul_rn(0.5f, nw));
    y1 = fminf(fmaxf(y1, 0.f), 1024.f);
    x1 = fminf(fmaxf(x1, 0.f), 1024.f);
    y2 = fminf(fmaxf(y2, 0.f), 1024.f);
    x2 = fminf(fmaxf(x2, 0.f), 1024.f);
    float hs = __fadd_rn(y2, -y1), ws = __fadd_rn(x2, -x1);
    float score = (hs >= 16.f && ws >= 16.f) ? p1 : -INFINITY;
    g_box[(size_t)b * NA + k] = make_float4(y1, x1, y2, x2);
    g_sco[(size_t)b * NA + k] = score;
}

// ---------------- 5: write all anchors to output -----------------------------
__global__ void k_wanchors(float* __restrict__ out) {
    size_t off = (size_t)g_K * 12 + 3000;
    for (int i = blockIdx.x * blockDim.x + threadIdx.x; i < NA * 4;
         i += gridDim.x * blockDim.x)
        out[off + i] = g_anc[i];
}

// ---------------- bitonic sorts (shared, n=2048, 1024 threads) ---------------
__device__ void bitonic2048_u64(unsigned long long* buf, int tid) {
    for (int k = 2; k <= 2048; k <<= 1)
        for (int j = k >> 1; j > 0; j >>= 1) {
            for (int i = tid; i < 2048; i += 1024) {
                int ixj = i ^ j;
                if (ixj > i) {
                    unsigned long long a = buf[i], c = buf[ixj];
                    bool up = ((i & k) == 0);
                    if ((a > c) == up) { buf[i] = c; buf[ixj] = a; }
                }
            }
            __syncthreads();
        }
}
__device__ void bitonic2048_u32(unsigned* buf, int tid) {
    for (int k = 2; k <= 2048; k <<= 1)
        for (int j = k >> 1; j > 0; j >>= 1) {
            for (int i = tid; i < 2048; i += 1024) {
                int ixj = i ^ j;
                if (ixj > i) {
                    unsigned a = buf[i], c = buf[ixj];
                    bool up = ((i & k) == 0);
                    if ((a > c) == up) { buf[i] = c; buf[ixj] = a; }
                }
            }
            __syncthreads();
        }
}

// ---------------- 6: exact top-2000 (radix select + sort), per batch ---------
__global__ void k_topk() {
    int b = blockIdx.x;
    int tid = threadIdx.x;                 // 1024
    int N = g_K;
    const float* sc = g_sco + (size_t)b * NA;
    __shared__ unsigned hist[256];
    __shared__ unsigned long long sbuf[2048];
    __shared__ unsigned idxbuf[2048];
    __shared__ int s_bin, s_need, s_cgt, s_ceq;

    unsigned prefix = 0;
    int need = PRE;
    for (int shift = 24; shift >= 0; shift -= 8) {
        if (tid < 256) hist[tid] = 0;
        __syncthreads();
        unsigned himask = (shift == 24) ? 0u : (0xFFFFFFFFu << (shift + 8));
        for (int i = tid; i < N; i += 1024) {
            unsigned key = fkey(sc[i]);
            if ((key & himask) == prefix) atomicAdd(&hist[(key >> shift) & 255u], 1u);
        }
        __syncthreads();
        if (tid == 0) {
            int nd = need, bin = 255;
            for (; bin >= 0; --bin) {
                int c = (int)hist[bin];
                if (nd <= c) break;
                nd -= c;
            }
            s_bin = bin; s_need = nd;
        }
        __syncthreads();
        prefix |= ((unsigned)s_bin) << shift;
        need = s_need;
        __syncthreads();
    }
    unsigned T = prefix;   // exact 2000th-largest key; need = count to take among ==T

    if (tid == 0) { s_cgt = 0; s_ceq = 0; }
    for (int i = tid; i < 2048; i += 1024) { sbuf[i] = ~0ULL; idxbuf[i] = 0xFFFFFFFFu; }
    __syncthreads();
    for (int i = tid; i < N; i += 1024) {
        unsigned key = fkey(sc[i]);
        if (key > T) {
            int p = atomicAdd(&s_cgt, 1);
            sbuf[p] = (((unsigned long long)(~key)) << 32) | (unsigned)i;
        } else if (key == T) {
            int p = atomicAdd(&s_ceq, 1);
            if (p < 2048) idxbuf[p] = (unsigned)i;
        }
    }
    __syncthreads();
    bitonic2048_u32(idxbuf, tid);          // smallest indices first among ties
    int cgt = s_cgt;
    for (int t2 = tid; t2 < need; t2 += 1024)
        sbuf[cgt + t2] = (((unsigned long long)(~T)) << 32) | idxbuf[t2];
    __syncthreads();
    bitonic2048_u64(sbuf, tid);            // (score desc, idx asc)
    for (int t2 = tid; t2 < PRE; t2 += 1024) {
        unsigned idx = (unsigned)(sbuf[t2] & 0xFFFFFFFFu);
        g_tb[b * PRE + t2] = g_box[(size_t)b * NA + idx];
        g_ts[b * PRE + t2] = sc[idx];
    }
}

// ---------------- 7: greedy NMS over sorted candidates, per batch ------------
__global__ void k_nms(float* __restrict__ out) {
    int b = blockIdx.x;
    int tid = threadIdx.x;                 // 256
    int K = g_K;
    size_t OFF_ROI = (size_t)K * 12;
    size_t OFF_ID  = OFF_ROI + 2400;
    __shared__ float by1[PRE], bx1[PRE], by2[PRE], bx2[PRE], bar[PRE];
    __shared__ int alive[PRE];
    __shared__ int s_cur, s_kept, s_p;
    for (int i = tid; i < PRE; i += blockDim.x) {
        float4 bb = g_tb[b * PRE + i];
        by1[i] = bb.x; bx1[i] = bb.y; by2[i] = bb.z; bx2[i] = bb.w;
        bar[i] = __fmul_rn(__fadd_rn(bb.z, -bb.x), __fadd_rn(bb.w, -bb.y));
        alive[i] = (g_ts[b * PRE + i] > -INFINITY) ? 1 : 0;
    }
    if (tid == 0) { s_kept = 0; s_p = 0; }
    __syncthreads();
    while (true) {
        if (tid == 0) {
            int p = s_p;
            while (p < PRE && !alive[p]) p++;
            if (p < PRE && s_kept < POST) {
                alive[p] = 0;
                int kk = s_kept++;
                float* ro = out + OFF_ROI + ((size_t)b * POST + kk) * 4;
                ro[0] = by1[p]; ro[1] = bx1[p]; ro[2] = by2[p]; ro[3] = bx2[p];
                s_cur = p;
                s_p = p + 1;
            } else s_cur = -1;
        }
        __syncthreads();
        int cur = s_cur;
        if (cur < 0) break;
        float py1 = by1[cur], px1 = bx1[cur], py2 = by2[cur], px2 = bx2[cur], pa = bar[cur];
        for (int j = cur + 1 + tid; j < PRE; j += blockDim.x) {
            if (!alive[j]) continue;
            float yy1 = fmaxf(py1, by1[j]);
            float xx1 = fmaxf(px1, bx1[j]);
            float yy2 = fminf(py2, by2[j]);
            float xx2 = fminf(px2, bx2[j]);
            float inter = __fmul_rn(fmaxf(__fadd_rn(yy2, -yy1), 0.f),
                                    fmaxf(__fadd_rn(xx2, -xx1), 0.f));
            float denom = __fadd_rn(__fadd_rn(__fadd_rn(pa, bar[j]), -inter), 1e-9f);
            if (__fdiv_rn(inter, denom) > 0.7f) alive[j] = 0;
        }
        __syncthreads();
    }
    for (int i = tid; i < POST; i += blockDim.x) {
        if (i >= s_kept) {
            float* ro = out + OFF_ROI + ((size_t)b * POST + i) * 4;
            ro[0] = 0.f; ro[1] = 0.f; ro[2] = 0.f; ro[3] = 0.f;
        }
        out[OFF_ID + b * POST + i] = (float)b;
    }
}

// ---------------- launch ----------------
extern "C" void kernel_launch(void* const* d_in, const int* in_sizes, int n_in,
                              void* d_out, int out_size) {
    const float* feat    = (const float*)d_in[0];
    const float* share_w = (const float*)d_in[1];
    const float* share_b = (const float*)d_in[2];
    const float* cls_w   = (const float*)d_in[3];
    const float* cls_b   = (const float*)d_in[4];
    const float* reg_w   = (const float*)d_in[5];
    const float* reg_b   = (const float*)d_in[6];
    float* out = (float*)d_out;

    k_wsplit<<<(512 * KSZ + 255) / 256, 256>>>(share_w);
    k_fsplit<<<(FPLANE + 255) / 256, 256>>>(feat);
    k_anchors<<<1, 1024>>>();
    k_conv1mma<<<dim3(64, 8), 256>>>(share_b);
    k_conv2<<<128, 512>>>(cls_w, cls_b, reg_w, reg_b);
    k_decode<<<(2 * NA + 255) / 256, 256>>>(out);
    k_wanchors<<<576, 256>>>(out);
    k_topk<<<2, 1024>>>();
    k_nms<<<2, 256>>>(out);
}

// round 6
// speedup vs baseline: 2.0142x; 1.5474x over previous
#include <cuda_runtime.h>
#include <math.h>

#define NB 2
#define NC 512
#define NH 64
#define NW 64
#define NHW 4096
#define NA 36864      // H*W*9 anchors
#define KSZ 4608      // 512*9
#define PRE 2000
#define POST 300

// shifted halo'd feat planes: [p*3+dx][bc][66 rows][80 cols]
#define FROW 80
#define FHROWS 66
#define FPL ((size_t)NB * NC * FHROWS * FROW)

// ---------------- scratch (device globals; no allocation) ----------------
__device__ __align__(16) unsigned short g_ws[3][(size_t)512 * KSZ];  // weight planes [o][k]
__device__ __align__(16) unsigned short g_fsx[9][FPL];               // feat planes, shifted
__device__ float  g_shr[(size_t)NB * NC * NHW];     // shared conv output (NCHW)
__device__ float  g_act[(size_t)NB * NHW * 54];     // cls(18)+reg(36) logits, (b,pos,54)
__device__ float  g_anc[NA * 4];
__device__ int    g_val[NA];
__device__ int    g_K;
__device__ float4 g_box[NB * NA];
__device__ float  g_sco[NB * NA];
__device__ float4 g_tb[NB * PRE];
__device__ float  g_ts[NB * PRE];
__device__ unsigned g_mask[(size_t)NB * PRE * 64];  // NMS IoU bitmask

// ---------------- helpers ----------------
__device__ __forceinline__ unsigned fkey(float f) {
    unsigned u = __float_as_uint(f);
    return (u & 0x80000000u) ? ~u : (u | 0x80000000u);
}
__device__ __forceinline__ unsigned smem_u32(const void* p) {
    unsigned a;
    asm("{ .reg .u64 t; cvta.to.shared.u64 t, %1; cvt.u32.u64 %0, t; }" : "=r"(a) : "l"(p));
    return a;
}
__device__ __forceinline__ unsigned bf16hi(float v) {
    unsigned u = __float_as_uint(v);
    return (u + 0x7FFFu + ((u >> 16) & 1u)) & 0xFFFF0000u;
}
__device__ __forceinline__ void split3(float v, unsigned short& h, unsigned short& m,
                                       unsigned short& l) {
    unsigned rh = bf16hi(v);
    float r1 = v - __uint_as_float(rh);
    unsigned rm = bf16hi(r1);
    float r2 = r1 - __uint_as_float(rm);
    unsigned rl = bf16hi(r2);
    h = (unsigned short)(rh >> 16);
    m = (unsigned short)(rm >> 16);
    l = (unsigned short)(rl >> 16);
}
#define CP_ASYNC16(dst, src) \
    asm volatile("cp.async.ca.shared.global [%0], [%1], 16;" \
                 :: "r"(dst), "l"(src) : "memory")
#define CP_COMMIT() asm volatile("cp.async.commit_group;" ::: "memory")
#define CP_WAIT0()  asm volatile("cp.async.wait_group 0;" ::: "memory")
__device__ __forceinline__ void ldmx4(unsigned* r, unsigned addr) {
    asm volatile("ldmatrix.sync.aligned.m8n8.x4.shared.b16 {%0,%1,%2,%3}, [%4];"
                 : "=r"(r[0]), "=r"(r[1]), "=r"(r[2]), "=r"(r[3]) : "r"(addr));
}
__device__ __forceinline__ void ldmx4t(unsigned* r, unsigned addr) {
    asm volatile("ldmatrix.sync.aligned.m8n8.x4.trans.shared.b16 {%0,%1,%2,%3}, [%4];"
                 : "=r"(r[0]), "=r"(r[1]), "=r"(r[2]), "=r"(r[3]) : "r"(addr));
}
__device__ __forceinline__ void mma16816(float* c, const unsigned* a, unsigned b0,
                                         unsigned b1) {
    asm volatile(
        "mma.sync.aligned.m16n8k16.row.col.f32.bf16.bf16.f32 "
        "{%0,%1,%2,%3},{%4,%5,%6,%7},{%8,%9},{%0,%1,%2,%3};"
        : "+f"(c[0]), "+f"(c[1]), "+f"(c[2]), "+f"(c[3])
        : "r"(a[0]), "r"(a[1]), "r"(a[2]), "r"(a[3]), "r"(b0), "r"(b1));
}

// ---------------- 0a: split weights into 3 bf16 planes [o][k] ----------------
__global__ void k_wsplit(const float* __restrict__ w) {
    int i = blockIdx.x * blockDim.x + threadIdx.x;
    if (i < 512 * KSZ) {
        unsigned short h, m, l;
        split3(w[i], h, m, l);
        g_ws[0][i] = h; g_ws[1][i] = m; g_ws[2][i] = l;
    }
}

// -------- 0b: split feat into 9 shifted bf16 planes (p, dx), zero halo -------
// plane pd = p*3+dx: entry [bc][yy][xi] = feat[bc][yy-1][xi+dx-1] (0 if OOB)
__global__ void k_fsplit9(const float* __restrict__ feat) {
    size_t i = (size_t)blockIdx.x * blockDim.x + threadIdx.x;
    if (i >= 9 * FPL) return;
    int pd = (int)(i / FPL);
    int p = pd / 3, dx = pd - p * 3;
    size_t rem = i - (size_t)pd * FPL;
    int bc = (int)(rem / (FHROWS * FROW));
    int r2 = (int)(rem - (size_t)bc * (FHROWS * FROW));
    int yy = r2 / FROW, xi = r2 - yy * FROW;
    int yf = yy - 1, xf = xi + dx - 1;
    float v = 0.f;
    if ((unsigned)yf < 64u && (unsigned)xf < 64u)
        v = feat[(size_t)bc * NHW + yf * 64 + xf];
    unsigned short h, m, l;
    split3(v, h, m, l);
    g_fsx[pd][rem] = (p == 0) ? h : (p == 1 ? m : l);
}

// ---------------- 1: anchors + valid compaction (single block) ----------------
__global__ void k_anchors() {
    __shared__ float sbase[9][4];
    __shared__ int s_scan[1024];
    __shared__ int s_carry;
    int tid = threadIdx.x;
    if (tid == 0) {
        double ratios[3] = {0.5, 1.0, 2.0};
        double scales[3] = {8.0, 16.0, 32.0};
        int k = 0;
        for (int ri = 0; ri < 3; ri++)
            for (int si = 0; si < 3; si++) {
                double h = 16.0 * scales[si] * sqrt(ratios[ri]);
                double w = 16.0 * scales[si] * sqrt(1.0 / ratios[ri]);
                sbase[k][0] = (float)(8.0 - h / 2.0);
                sbase[k][1] = (float)(8.0 - w / 2.0);
                sbase[k][2] = (float)(8.0 + h / 2.0);
                sbase[k][3] = (float)(8.0 + w / 2.0);
                k++;
            }
        s_carry = 0;
    }
    __syncthreads();
    for (int c0 = 0; c0 < NA; c0 += 1024) {
        int a = c0 + tid;
        int pos = a / 9, j = a - pos * 9;
        int gy = pos >> 6, gx = pos & 63;
        float y1 = gy * 16.f + sbase[j][0];
        float x1 = gx * 16.f + sbase[j][1];
        float y2 = gy * 16.f + sbase[j][2];
        float x2 = gx * 16.f + sbase[j][3];
        g_anc[a * 4 + 0] = y1; g_anc[a * 4 + 1] = x1;
        g_anc[a * 4 + 2] = y2; g_anc[a * 4 + 3] = x2;
        int v = (y1 >= 0.f && x1 >= 0.f && y2 <= 1024.f && x2 <= 1024.f) ? 1 : 0;
        s_scan[tid] = v;
        __syncthreads();
        for (int off = 1; off < 1024; off <<= 1) {
            int t = (tid >= off) ? s_scan[tid - off] : 0;
            __syncthreads();
            s_scan[tid] += t;
            __syncthreads();
        }
        if (v) g_val[s_carry + s_scan[tid] - 1] = a;
        __syncthreads();
        if (tid == 0) s_carry += s_scan[1023];
        __syncthreads();
    }
    if (tid == 0) g_K = s_carry;
}

// ---- 2: 3x3 conv via mma.sync bf16 3-way split, cp.async double buffer ------
// GEMM C[8192][512] = im2col(feat)[8192][4608] x W^T; CTA 128x64, kstep 32.
#define ASTRIDE 136                       // halves per A k-row (272B)
#define BSTRIDE 40                        // halves per B n-row (80B)
#define ABYTES  (3 * 32 * ASTRIDE * 2)    // 26112
#define BBYTES  (3 * 64 * BSTRIDE * 2)    // 15360
#define BUFBYTES (ABYTES + BBYTES)        // 41472
#define SMEM_CONV (2 * BUFBYTES)          // 82944

__global__ __launch_bounds__(256, 2) void k_conv1mma(const float* __restrict__ bias) {
    extern __shared__ __align__(16) unsigned short dyn[];
    const unsigned sb = smem_u32(dyn);
    const int tid = threadIdx.x;
    const int wid = tid >> 5, lane = tid & 31;
    const int wm = wid & 3, wn = wid >> 2;
    const int m0 = blockIdx.x * 128;
    const int n0 = blockIdx.y * 64;
    const int b = m0 >> 12;
    const int y0 = (m0 >> 6) & 63;

    float acc[2][4][4] = {};

    // per-thread ldmatrix address components
    const int a_krow = (lane & 7) + (((lane >> 4) & 1) << 3);
    const int a_moff = ((lane >> 3) & 1) << 3;
    const int b_nrow = wn * 32 + (((lane >> 4) & 1) << 3) + (lane & 7);
    const int b_koff = ((lane >> 3) & 1) << 3;

    auto issue = [&](int ch, int buf) {
        const int k0 = ch * 32;
        const unsigned abase = sb + buf * BUFBYTES;
        const unsigned bbase = abase + ABYTES;
#pragma unroll
        for (int it = 0; it < 6; ++it) {
            int t = tid + (it << 8);
            int p = t >> 9;
            int rem = t & 511;
            int kk = rem >> 4, oct = rem & 15;
            int k = k0 + kk;
            int c = k / 9;
            int r = k - c * 9;
            int dy = r / 3, dx = r - dy * 3;
            int y = y0 + (oct >> 3);
            int x0 = (oct & 7) << 3;
            const unsigned short* src =
                &g_fsx[p * 3 + dx][((size_t)(b * NC + c) * FHROWS + (y + dy)) * FROW + x0];
            unsigned dst = abase + p * (32 * ASTRIDE * 2) + kk * (ASTRIDE * 2) + oct * 16;
            CP_ASYNC16(dst, src);
        }
#pragma unroll
        for (int it = 0; it < 3; ++it) {
            int t = tid + (it << 8);
            int p = t >> 8;
            int rem = t & 255;
            int n = rem >> 2, kq = rem & 3;
            const unsigned short* src = &g_ws[p][(size_t)(n0 + n) * KSZ + k0 + (kq << 3)];
            unsigned dst = bbase + p * (64 * BSTRIDE * 2) + n * (BSTRIDE * 2) + kq * 16;
            CP_ASYNC16(dst, src);
        }
        CP_COMMIT();
    };

    issue(0, 0);

#pragma unroll 1
    for (int ch = 0; ch < KSZ / 32; ++ch) {
        CP_WAIT0();
        __syncthreads();
        if (ch + 1 < KSZ / 32) issue(ch + 1, (ch + 1) & 1);
        const unsigned sbA = sb + (ch & 1) * BUFBYTES;
        const unsigned sbB = sbA + ABYTES;
#pragma unroll
        for (int step = 0; step < 2; ++step) {
            const int k16 = step << 4;
            unsigned af[3][2][4], bf[3][2][4];
#pragma unroll
            for (int p = 0; p < 3; ++p) {
#pragma unroll
                for (int i = 0; i < 2; ++i)
                    ldmx4t(af[p][i], sbA + p * (32 * ASTRIDE * 2) +
                                     (k16 + a_krow) * (ASTRIDE * 2) +
                                     (wm * 32 + i * 16 + a_moff) * 2);
#pragma unroll
                for (int jj = 0; jj < 2; ++jj)
                    ldmx4(bf[p][jj], sbB + p * (64 * BSTRIDE * 2) +
                                     (b_nrow + jj * 16) * (BSTRIDE * 2) +
                                     (k16 + b_koff) * 2);
            }
            const int pa[6] = {0, 0, 1, 0, 1, 2};
            const int pb[6] = {0, 1, 0, 2, 1, 0};
#pragma unroll
            for (int q = 0; q < 6; ++q)
#pragma unroll
                for (int i = 0; i < 2; ++i)
#pragma unroll
                    for (int j = 0; j < 4; ++j)
                        mma16816(acc[i][j], af[pa[q]][i],
                                 bf[pb[q]][j >> 1][(j & 1) * 2],
                                 bf[pb[q]][j >> 1][(j & 1) * 2 + 1]);
        }
        __syncthreads();
    }

    // ---- epilogue: bias + relu -> g_shr (NCHW) ----
    const int mb = m0 + wm * 32 + (lane >> 2);
    const int nb = n0 + wn * 32 + ((lane & 3) << 1);
#pragma unroll
    for (int i = 0; i < 2; ++i) {
#pragma unroll
        for (int j = 0; j < 4; ++j) {
            int o = nb + j * 8;
            float b0v = bias[o], b1v = bias[o + 1];
            int m_a = mb + i * 16;
            int m_b = m_a + 8;
            size_t pa_ = ((size_t)(b * NC + o) << 12);
            size_t pb_ = ((size_t)(b * NC + o + 1) << 12);
            g_shr[pa_ + (m_a & 4095)] = fmaxf(acc[i][j][0] + b0v, 0.f);
            g_shr[pb_ + (m_a & 4095)] = fmaxf(acc[i][j][1] + b1v, 0.f);
            g_shr[pa_ + (m_b & 4095)] = fmaxf(acc[i][j][2] + b0v, 0.f);
            g_shr[pb_ + (m_b & 4095)] = fmaxf(acc[i][j][3] + b1v, 0.f);
        }
    }
}

// ---------------- 3: 1x1 convs (cls 18 + reg 36 = 54 outputs) ----------------
__global__ void k_conv2(const float* __restrict__ cls_w, const float* __restrict__ cls_b,
                        const float* __restrict__ reg_w, const float* __restrict__ reg_b) {
    int blk = blockIdx.x;        // (b,y)
    int b = blk >> 6, y = blk & 63;
    __shared__ float sin_[64][64];
    __shared__ float sw[64][56];
    int tid = threadIdx.x;       // 512 threads
    int x = tid & 63, og = tid >> 6;
    float acc[7] = {};
    for (int c0 = 0; c0 < 512; c0 += 64) {
        for (int idx = tid; idx < 4096; idx += 512) {
            int c = idx >> 6, xx = idx & 63;
            sin_[c][xx] = g_shr[(((size_t)b * NC + c0 + c) * NH + y) * NW + xx];
        }
        for (int idx = tid; idx < 64 * 56; idx += 512) {
            int c = idx / 56, o = idx - c * 56;
            float v = 0.f;
            if (o < 18) v = cls_w[(size_t)o * 512 + c0 + c];
            else if (o < 54) v = reg_w[(size_t)(o - 18) * 512 + c0 + c];
            sw[c][o] = v;
        }
        __syncthreads();
#pragma unroll 8
        for (int c = 0; c < 64; ++c) {
            float a = sin_[c][x];
#pragma unroll
            for (int i = 0; i < 7; ++i) acc[i] += a * sw[c][og + 8 * i];
        }
        __syncthreads();
    }
    for (int i = 0; i < 7; ++i) {
        int o = og + 8 * i;
        if (o < 54) {
            float bs = (o < 18) ? cls_b[o] : reg_b[o - 18];
            g_act[((size_t)b * NHW + y * 64 + x) * 54 + o] = acc[i] + bs;
        }
    }
}

// ---------------- 4: gather + softmax + decode + clip + minsize --------------
__global__ void k_decode(float* __restrict__ out) {
    int K = g_K;
    int t = blockIdx.x * blockDim.x + threadIdx.x;
    if (t >= 2 * K) return;
    int b = t / K, k = t - b * K;
    int a = g_val[k];
    int pos = a / 9, j = a - pos * 9;
    const float* ab = g_act + ((size_t)b * NHW + pos) * 54;
    float l0 = ab[2 * j], l1 = ab[2 * j + 1];
    float m = fmaxf(l0, l1);
    float e0 = expf(__fadd_rn(l0, -m)), e1 = expf(__fadd_rn(l1, -m));
    float s = __fadd_rn(e0, e1);
    float p0 = __fdiv_rn(e0, s), p1 = __fdiv_rn(e1, s);
    out[(size_t)(b * K + k) * 2 + 0] = p0;
    out[(size_t)(b * K + k) * 2 + 1] = p1;
    float d0 = ab[18 + 4 * j], d1 = ab[19 + 4 * j], d2 = ab[20 + 4 * j], d3 = ab[21 + 4 * j];
    size_t ro = (size_t)4 * K;
    out[ro + (size_t)(b * K + k) * 4 + 0] = d0;
    out[ro + (size_t)(b * K + k) * 4 + 1] = d1;
    out[ro + (size_t)(b * K + k) * 4 + 2] = d2;
    out[ro + (size_t)(b * K + k) * 4 + 3] = d3;
    float ay1 = g_anc[a * 4 + 0], ax1 = g_anc[a * 4 + 1];
    float ay2 = g_anc[a * 4 + 2], ax2 = g_anc[a * 4 + 3];
    float h  = __fadd_rn(ay2, -ay1);
    float w  = __fadd_rn(ax2, -ax1);
    float cy = __fadd_rn(ay1, __fmul_rn(0.5f, h));
    float cx = __fadd_rn(ax1, __fmul_rn(0.5f, w));
    float ncy = __fadd_rn(__fmul_rn(d0, h), cy);
    float ncx = __fadd_rn(__fmul_rn(d1, w), cx);
    float nh = __fmul_rn(h, expf(d2));
    float nw = __fmul_rn(w, expf(d3));
    float y1 = __fadd_rn(ncy, -__fmul_rn(0.5f, nh));
    float x1 = __fadd_rn(ncx, -__fmul_rn(0.5f, nw));
    float y2 = __fadd_rn(ncy,  __fmul_rn(0.5f, nh));
    float x2 = __fadd_rn(ncx,  __fmul_rn(0.5f, nw));
    y1 = fminf(fmaxf(y1, 0.f), 1024.f);
    x1 = fminf(fmaxf(x1, 0.f), 1024.f);
    y2 = fminf(fmaxf(y2, 0.f), 1024.f);
    x2 = fminf(fmaxf(x2, 0.f), 1024.f);
    float hs = __fadd_rn(y2, -y1), ws = __fadd_rn(x2, -x1);
    float score = (hs >= 16.f && ws >= 16.f) ? p1 : -INFINITY;
    g_box[(size_t)b * NA + k] = make_float4(y1, x1, y2, x2);
    g_sco[(size_t)b * NA + k] = score;
}

// ---------------- 5: write all anchors to output -----------------------------
__global__ void k_wanchors(float* __restrict__ out) {
    size_t off = (size_t)g_K * 12 + 3000;
    for (int i = blockIdx.x * blockDim.x + threadIdx.x; i < NA * 4;
         i += gridDim.x * blockDim.x)
        out[off + i] = g_anc[i];
}

// ---------------- bitonic sorts (shared, n=2048, 1024 threads) ---------------
__device__ void bitonic2048_u64(unsigned long long* buf, int tid) {
    for (int k = 2; k <= 2048; k <<= 1)
        for (int j = k >> 1; j > 0; j >>= 1) {
            for (int i = tid; i < 2048; i += 1024) {
                int ixj = i ^ j;
                if (ixj > i) {
                    unsigned long long a = buf[i], c = buf[ixj];
                    bool up = ((i & k) == 0);
                    if ((a > c) == up) { buf[i] = c; buf[ixj] = a; }
                }
            }
            __syncthreads();
        }
}
__device__ void bitonic2048_u32(unsigned* buf, int tid) {
    for (int k = 2; k <= 2048; k <<= 1)
        for (int j = k >> 1; j > 0; j >>= 1) {
            for (int i = tid; i < 2048; i += 1024) {
                int ixj = i ^ j;
                if (ixj > i) {
                    unsigned a = buf[i], c = buf[ixj];
                    bool up = ((i & k) == 0);
                    if ((a > c) == up) { buf[i] = c; buf[ixj] = a; }
                }
            }
            __syncthreads();
        }
}

// ---------------- 6: exact top-2000 (radix select + sort), per batch ---------
__global__ void k_topk() {
    int b = blockIdx.x;
    int tid = threadIdx.x;                 // 1024
    int N = g_K;
    const float* sc = g_sco + (size_t)b * NA;
    __shared__ unsigned hist[256];
    __shared__ unsigned long long sbuf[2048];
    __shared__ unsigned idxbuf[2048];
    __shared__ int s_bin, s_need, s_cgt, s_ceq;

    unsigned prefix = 0;
    int need = PRE;
    for (int shift = 24; shift >= 0; shift -= 8) {
        if (tid < 256) hist[tid] = 0;
        __syncthreads();
        unsigned himask = (shift == 24) ? 0u : (0xFFFFFFFFu << (shift + 8));
        for (int i = tid; i < N; i += 1024) {
            unsigned key = fkey(sc[i]);
            if ((key & himask) == prefix) atomicAdd(&hist[(key >> shift) & 255u], 1u);
        }
        __syncthreads();
        if (tid == 0) {
            int nd = need, bin = 255;
            for (; bin >= 0; --bin) {
                int c = (int)hist[bin];
                if (nd <= c) break;
                nd -= c;
            }
            s_bin = bin; s_need = nd;
        }
        __syncthreads();
        prefix |= ((unsigned)s_bin) << shift;
        need = s_need;
        __syncthreads();
    }
    unsigned T = prefix;

    if (tid == 0) { s_cgt = 0; s_ceq = 0; }
    for (int i = tid; i < 2048; i += 1024) { sbuf[i] = ~0ULL; idxbuf[i] = 0xFFFFFFFFu; }
    __syncthreads();
    for (int i = tid; i < N; i += 1024) {
        unsigned key = fkey(sc[i]);
        if (key > T) {
            int p = atomicAdd(&s_cgt, 1);
            sbuf[p] = (((unsigned long long)(~key)) << 32) | (unsigned)i;
        } else if (key == T) {
            int p = atomicAdd(&s_ceq, 1);
            if (p < 2048) idxbuf[p] = (unsigned)i;
        }
    }
    __syncthreads();
    bitonic2048_u32(idxbuf, tid);
    int cgt = s_cgt;
    for (int t2 = tid; t2 < need; t2 += 1024)
        sbuf[cgt + t2] = (((unsigned long long)(~T)) << 32) | idxbuf[t2];
    __syncthreads();
    bitonic2048_u64(sbuf, tid);
    for (int t2 = tid; t2 < PRE; t2 += 1024) {
        unsigned idx = (unsigned)(sbuf[t2] & 0xFFFFFFFFu);
        g_tb[b * PRE + t2] = g_box[(size_t)b * NA + idx];
        g_ts[b * PRE + t2] = sc[idx];
    }
}

// ---------------- 7a: parallel IoU suppression bitmask -----------------------
__global__ void k_iou() {
    __shared__ float4 jb[64];
    __shared__ float ja[64];
    int b = blockIdx.z;
    int ti = threadIdx.x;      // 64
    int j0 = blockIdx.y * 64;
    float4 bb = make_float4(0.f, 0.f, 0.f, 0.f);
    if (j0 + ti < PRE) bb = g_tb[b * PRE + j0 + ti];
    jb[ti] = bb;
    ja[ti] = __fmul_rn(__fadd_rn(bb.z, -bb.x), __fadd_rn(bb.w, -bb.y));
    __syncthreads();
    int i = blockIdx.x * 64 + ti;
    if (i >= PRE) return;
    float4 bi = g_tb[b * PRE + i];
    float ai = __fmul_rn(__fadd_rn(bi.z, -bi.x), __fadd_rn(bi.w, -bi.y));
    unsigned w0 = 0, w1 = 0;
#pragma unroll
    for (int jj = 0; jj < 64; ++jj) {
        float4 bj = jb[jj];
        float yy1 = fmaxf(bi.x, bj.x), xx1 = fmaxf(bi.y, bj.y);
        float yy2 = fminf(bi.z, bj.z), xx2 = fminf(bi.w, bj.w);
        float inter = __fmul_rn(fmaxf(__fadd_rn(yy2, -yy1), 0.f),
                                fmaxf(__fadd_rn(xx2, -xx1), 0.f));
        float denom = __fadd_rn(__fadd_rn(__fadd_rn(ai, ja[jj]), -inter), 1e-9f);
        if (__fdiv_rn(inter, denom) > 0.7f) {
            if (jj < 32) w0 |= 1u << jj; else w1 |= 1u << (jj - 32);
        }
    }
    size_t mb = ((size_t)b * PRE + i) * 64 + blockIdx.y * 2;
    g_mask[mb] = w0;
    g_mask[mb + 1] = w1;
}

// ---------------- 7b: single-warp bitset greedy scan -------------------------
__global__ void k_nms_scan(float* __restrict__ out) {
    int b = blockIdx.x;
    int lane = threadIdx.x;    // 32
    int K = g_K;
    size_t OFF_ROI = (size_t)K * 12;
    size_t OFF_ID  = OFF_ROI + 2400;
    __shared__ unsigned supp[63], valid[63];
    for (int w = lane; w < 63; w += 32) {
        unsigned v = 0;
        for (int bit = 0; bit < 32; ++bit) {
            int i = w * 32 + bit;
            if (i < PRE && g_ts[b * PRE + i] > -INFINITY) v |= 1u << bit;
        }
        valid[w] = v;
        supp[w] = 0;
    }
    __syncwarp();
    int kept = 0;
    for (int w = 0; w < 63 && kept < POST; ++w) {
        while (kept < POST) {
            unsigned live = valid[w] & ~supp[w];
            if (!live) break;
            int bit = __ffs(live) - 1;
            int i = w * 32 + bit;
            if (lane == 0) {
                float4 bbx = g_tb[b * PRE + i];
                float* ro = out + OFF_ROI + ((size_t)b * POST + kept) * 4;
                ro[0] = bbx.x; ro[1] = bbx.y; ro[2] = bbx.z; ro[3] = bbx.w;
            }
            kept++;
            const unsigned* mrow = &g_mask[((size_t)b * PRE + i) * 64];
            unsigned ex0 = (lane == w) ? (1u << bit) : 0u;
            supp[lane] |= mrow[lane] | ex0;
            int w2 = lane + 32;
            if (w2 < 63) {
                unsigned ex1 = (w2 == w) ? (1u << bit) : 0u;
                supp[w2] |= mrow[w2] | ex1;
            }
            __syncwarp();
        }
    }
    for (int i = lane; i < POST; i += 32) {
        if (i >= kept) {
            float* ro = out + OFF_ROI + ((size_t)b * POST + i) * 4;
            ro[0] = 0.f; ro[1] = 0.f; ro[2] = 0.f; ro[3] = 0.f;
        }
        out[OFF_ID + b * POST + i] = (float)b;
    }
}

// ---------------- launch ----------------
extern "C" void kernel_launch(void* const* d_in, const int* in_sizes, int n_in,
                              void* d_out, int out_size) {
    const float* feat    = (const float*)d_in[0];
    const float* share_w = (const float*)d_in[1];
    const float* share_b = (const float*)d_in[2];
    const float* cls_w   = (const float*)d_in[3];
    const float* cls_b   = (const float*)d_in[4];
    const float* reg_w   = (const float*)d_in[5];
    const float* reg_b   = (const float*)d_in[6];
    float* out = (float*)d_out;

    cudaFuncSetAttribute(k_conv1mma, cudaFuncAttributeMaxDynamicSharedMemorySize, SMEM_CONV);

    k_wsplit<<<(512 * KSZ + 255) / 256, 256>>>(share_w);
    k_fsplit9<<<(int)((9 * FPL + 255) / 256), 256>>>(feat);
    k_anchors<<<1, 1024>>>();
    k_conv1mma<<<dim3(64, 8), 256, SMEM_CONV>>>(share_b);
    k_conv2<<<128, 512>>>(cls_w, cls_b, reg_w, reg_b);
    k_decode<<<(2 * NA + 255) / 256, 256>>>(out);
    k_wanchors<<<576, 256>>>(out);
    k_topk<<<2, 1024>>>();
    k_iou<<<dim3(32, 32, 2), 64>>>();
    k_nms_scan<<<2, 32>>>(out);
}

// round 7
// speedup vs baseline: 2.1893x; 1.0869x over previous
#include <cuda_runtime.h>
#include <math.h>

#define NB 2
#define NC 512
#define NH 64
#define NW 64
#define NHW 4096
#define NA 36864      // H*W*9 anchors
#define KSZ 4608      // 512*9
#define PRE 2000
#define POST 300

// shifted halo'd feat planes: [p*3+dx][bc][66 rows][80 cols]
#define FROW 80
#define FHROWS 66
#define FPL ((size_t)NB * NC * FHROWS * FROW)

// ---------------- scratch (device globals; no allocation) ----------------
__device__ __align__(16) unsigned short g_ws[3][(size_t)512 * KSZ];  // weight planes [o][k]
__device__ __align__(16) unsigned short g_fsx[9][FPL];               // feat planes, shifted
__device__ float  g_shr[(size_t)NB * NC * NHW];     // shared conv output (NCHW)
__device__ float  g_act[(size_t)NB * NHW * 54];     // cls(18)+reg(36) logits, (b,pos,54)
__device__ float  g_anc[NA * 4];
__device__ int    g_val[NA];
__device__ int    g_K;
__device__ float4 g_box[NB * NA];
__device__ float  g_sco[NB * NA];
__device__ float4 g_tb[NB * PRE];
__device__ float  g_ts[NB * PRE];
__device__ unsigned g_mask[(size_t)NB * PRE * 64];  // NMS IoU bitmask

// ---------------- helpers ----------------
__device__ __forceinline__ unsigned fkey(float f) {
    unsigned u = __float_as_uint(f);
    return (u & 0x80000000u) ? ~u : (u | 0x80000000u);
}
__device__ __forceinline__ unsigned smem_u32(const void* p) {
    unsigned a;
    asm("{ .reg .u64 t; cvta.to.shared.u64 t, %1; cvt.u32.u64 %0, t; }" : "=r"(a) : "l"(p));
    return a;
}
__device__ __forceinline__ unsigned bf16hi(float v) {
    unsigned u = __float_as_uint(v);
    return (u + 0x7FFFu + ((u >> 16) & 1u)) & 0xFFFF0000u;
}
__device__ __forceinline__ void split3(float v, unsigned short& h, unsigned short& m,
                                       unsigned short& l) {
    unsigned rh = bf16hi(v);
    float r1 = v - __uint_as_float(rh);
    unsigned rm = bf16hi(r1);
    float r2 = r1 - __uint_as_float(rm);
    unsigned rl = bf16hi(r2);
    h = (unsigned short)(rh >> 16);
    m = (unsigned short)(rm >> 16);
    l = (unsigned short)(rl >> 16);
}
#define CP_ASYNC16(dst, src) \
    asm volatile("cp.async.cg.shared.global [%0], [%1], 16;" \
                 :: "r"(dst), "l"(src) : "memory")
#define CP_COMMIT() asm volatile("cp.async.commit_group;" ::: "memory")
#define CP_WAIT2()  asm volatile("cp.async.wait_group 2;" ::: "memory")
__device__ __forceinline__ void ldmx4(unsigned* r, unsigned addr) {
    asm volatile("ldmatrix.sync.aligned.m8n8.x4.shared.b16 {%0,%1,%2,%3}, [%4];"
                 : "=r"(r[0]), "=r"(r[1]), "=r"(r[2]), "=r"(r[3]) : "r"(addr));
}
__device__ __forceinline__ void ldmx4t(unsigned* r, unsigned addr) {
    asm volatile("ldmatrix.sync.aligned.m8n8.x4.trans.shared.b16 {%0,%1,%2,%3}, [%4];"
                 : "=r"(r[0]), "=r"(r[1]), "=r"(r[2]), "=r"(r[3]) : "r"(addr));
}
__device__ __forceinline__ void mma16816(float* c, const unsigned* a, unsigned b0,
                                         unsigned b1) {
    asm volatile(
        "mma.sync.aligned.m16n8k16.row.col.f32.bf16.bf16.f32 "
        "{%0,%1,%2,%3},{%4,%5,%6,%7},{%8,%9},{%0,%1,%2,%3};"
        : "+f"(c[0]), "+f"(c[1]), "+f"(c[2]), "+f"(c[3])
        : "r"(a[0]), "r"(a[1]), "r"(a[2]), "r"(a[3]), "r"(b0), "r"(b1));
}

// ---------------- 0: fused prep: wsplit + fsplit(one split per source) + halo --
#define WSP_BLKS 9216    // 512*KSZ/256
#define FSP_BLKS 16384   // NB*NC*4096/256
#define HALO_BLKS 9216   // 9*1024*256/256
__global__ void k_prep(const float* __restrict__ w, const float* __restrict__ feat) {
    int blk = blockIdx.x;
    int tid = threadIdx.x;
    if (blk < WSP_BLKS) {
        int i = blk * 256 + tid;
        unsigned short h, m, l;
        split3(w[i], h, m, l);
        g_ws[0][i] = h; g_ws[1][i] = m; g_ws[2][i] = l;
    } else if (blk < WSP_BLKS + FSP_BLKS) {
        int i = (blk - WSP_BLKS) * 256 + tid;   // source over NB*NC*64*64
        int xs = i & 63;
        int ys = (i >> 6) & 63;
        int bc = i >> 12;
        unsigned short h, m, l;
        split3(feat[i], h, m, l);
        int yy = ys + 1;
        size_t rbase = ((size_t)bc * FHROWS + yy) * FROW;
#pragma unroll
        for (int dx = 0; dx < 3; ++dx) {
            int xi = xs - dx + 1;
            if (xi >= 0) {
                size_t off = rbase + xi;
                g_fsx[dx][off] = h;
                g_fsx[3 + dx][off] = m;
                g_fsx[6 + dx][off] = l;
            }
        }
    } else {
        int i = (blk - WSP_BLKS - FSP_BLKS) * 256 + tid;  // 9*1024*256
        int sub = i & 255;
        int rest = i >> 8;
        int bc = rest & 1023;
        int pd = rest >> 10;
        if (pd < 9) {
            int dx = pd % 3;
            size_t base = (size_t)bc * FHROWS * FROW;
            if (sub < 128) {
                int row = (sub >> 6) ? 65 : 0;
                int xi = sub & 63;
                g_fsx[pd][base + row * FROW + xi] = 0;
            } else {
                int which = (sub >> 6) & 1;
                int row = 1 + (sub & 63);
                if (which == 0 && dx == 0) g_fsx[pd][base + row * FROW + 0] = 0;
                if (which == 1 && dx == 2) g_fsx[pd][base + row * FROW + 63] = 0;
            }
        }
    }
}

// ---------------- 1: anchors + valid compaction (ballot scan) -----------------
__global__ void k_anchors() {
    __shared__ float sbase[9][4];
    __shared__ int warpsum[32];
    __shared__ int s_carry, s_total;
    int tid = threadIdx.x;
    int wid = tid >> 5, lane = tid & 31;
    if (tid == 0) {
        double ratios[3] = {0.5, 1.0, 2.0};
        double scales[3] = {8.0, 16.0, 32.0};
        int k = 0;
        for (int ri = 0; ri < 3; ri++)
            for (int si = 0; si < 3; si++) {
                double h = 16.0 * scales[si] * sqrt(ratios[ri]);
                double w = 16.0 * scales[si] * sqrt(1.0 / ratios[ri]);
                sbase[k][0] = (float)(8.0 - h / 2.0);
                sbase[k][1] = (float)(8.0 - w / 2.0);
                sbase[k][2] = (float)(8.0 + h / 2.0);
                sbase[k][3] = (float)(8.0 + w / 2.0);
                k++;
            }
        s_carry = 0;
    }
    __syncthreads();
    for (int c0 = 0; c0 < NA; c0 += 1024) {
        int a = c0 + tid;
        int pos = a / 9, j = a - pos * 9;
        int gy = pos >> 6, gx = pos & 63;
        float y1 = gy * 16.f + sbase[j][0];
        float x1 = gx * 16.f + sbase[j][1];
        float y2 = gy * 16.f + sbase[j][2];
        float x2 = gx * 16.f + sbase[j][3];
        g_anc[a * 4 + 0] = y1; g_anc[a * 4 + 1] = x1;
        g_anc[a * 4 + 2] = y2; g_anc[a * 4 + 3] = x2;
        int v = (y1 >= 0.f && x1 >= 0.f && y2 <= 1024.f && x2 <= 1024.f) ? 1 : 0;
        unsigned bal = __ballot_sync(0xFFFFFFFFu, v);
        int wpre = __popc(bal & ((1u << lane) - 1u));
        if (lane == 0) warpsum[wid] = __popc(bal);
        __syncthreads();
        if (wid == 0) {
            int val = warpsum[lane];
            int incl = val;
#pragma unroll
            for (int off = 1; off < 32; off <<= 1) {
                int t = __shfl_up_sync(0xFFFFFFFFu, incl, off);
                if (lane >= off) incl += t;
            }
            warpsum[lane] = incl - val;    // exclusive
            if (lane == 31) s_total = incl;
        }
        __syncthreads();
        if (v) g_val[s_carry + warpsum[wid] + wpre] = a;
        __syncthreads();
        if (tid == 0) s_carry += s_total;
        __syncthreads();
    }
    if (tid == 0) g_K = s_carry;
}

// ---- 2: 3x3 conv via mma.sync bf16 split, 4-stage chunk-16 cp.async ring ----
#define CH2 16
#define NCH2 (KSZ / CH2)                  // 288
#define ASTR 136                          // halves per A k-row (272B)
#define BSTR 24                           // halves per B n-row (48B)
#define A2BYTES (3 * 16 * ASTR * 2)       // 13056
#define B2BYTES (3 * 64 * BSTR * 2)       // 9216
#define STAGE (A2BYTES + B2BYTES)         // 22272
#define NSTG 4
#define SMEM_CONV (NSTG * STAGE)          // 89088

__global__ __launch_bounds__(256, 2) void k_conv1mma(const float* __restrict__ bias) {
    extern __shared__ __align__(16) unsigned short dyn[];
    const unsigned sb = smem_u32(dyn);
    const int tid = threadIdx.x;
    const int wid = tid >> 5, lane = tid & 31;
    const int wm = wid & 3, wn = wid >> 2;
    const int m0 = blockIdx.x * 128;
    const int n0 = blockIdx.y * 64;
    const int b = m0 >> 12;
    const int y0 = (m0 >> 6) & 63;

    float acc[2][4][4] = {};

    const int a_krow = (lane & 7) + (((lane >> 4) & 1) << 3);   // 0..15
    const int a_moff = ((lane >> 3) & 1) << 3;
    const int b_nrow = wn * 32 + (((lane >> 4) & 1) << 3) + (lane & 7);
    const int b_koff = ((lane >> 3) & 1) << 3;                  // 0 or 8

    auto issue = [&](int ch, int stg) {
        const int k0 = ch * CH2;
        const unsigned abase = sb + stg * STAGE;
        const unsigned bbase = abase + A2BYTES;
#pragma unroll
        for (int it = 0; it < 3; ++it) {            // A: 768 cp.async
            int idx = tid + (it << 8);
            int p = idx >> 8;
            int rem = idx & 255;
            int kk = rem >> 4, oct = rem & 15;
            int k = k0 + kk;
            int c = k / 9;
            int r = k - c * 9;
            int dy = r / 3, dx = r - dy * 3;
            int y = y0 + (oct >> 3);
            int x0 = (oct & 7) << 3;
            const unsigned short* src =
                &g_fsx[p * 3 + dx][((size_t)(b * NC + c) * FHROWS + (y + dy)) * FROW + x0];
            CP_ASYNC16(abase + p * 4352 + kk * 272 + oct * 16, src);
        }
#pragma unroll
        for (int it = 0; it < 2; ++it) {            // B: 384 cp.async
            int idx = tid + (it << 8);
            if (idx < 384) {
                int p = idx >> 7;
                int rem = idx & 127;
                int n = rem >> 1, kq = rem & 1;
                const unsigned short* src = &g_ws[p][(size_t)(n0 + n) * KSZ + k0 + (kq << 3)];
                CP_ASYNC16(bbase + p * 3072 + n * 48 + kq * 16, src);
            }
        }
        CP_COMMIT();
    };

    issue(0, 0); issue(1, 1); issue(2, 2);

#pragma unroll 1
    for (int ch = 0; ch < NCH2; ++ch) {
        CP_WAIT2();
        __syncthreads();
        if (ch + 3 < NCH2) issue(ch + 3, (ch + 3) & 3);
        const unsigned sbA = sb + (ch & 3) * STAGE;
        const unsigned sbB = sbA + A2BYTES;
        unsigned af[3][2][4], bf[3][2][4];
#pragma unroll
        for (int p = 0; p < 3; ++p) {
#pragma unroll
            for (int i = 0; i < 2; ++i)
                ldmx4t(af[p][i], sbA + p * 4352 + a_krow * 272 +
                                 (wm * 32 + i * 16 + a_moff) * 2);
#pragma unroll
            for (int jj = 0; jj < 2; ++jj)
                ldmx4(bf[p][jj], sbB + p * 3072 + (b_nrow + jj * 16) * 48 + b_koff * 2);
        }
        const int pa[6] = {0, 0, 1, 0, 1, 2};
        const int pb[6] = {0, 1, 0, 2, 1, 0};
#pragma unroll
        for (int q = 0; q < 6; ++q)
#pragma unroll
            for (int i = 0; i < 2; ++i)
#pragma unroll
                for (int j = 0; j < 4; ++j)
                    mma16816(acc[i][j], af[pa[q]][i],
                             bf[pb[q]][j >> 1][(j & 1) * 2],
                             bf[pb[q]][j >> 1][(j & 1) * 2 + 1]);
    }

    // ---- epilogue: bias + relu -> g_shr (NCHW) ----
    const int mb = m0 + wm * 32 + (lane >> 2);
    const int nb = n0 + wn * 32 + ((lane & 3) << 1);
#pragma unroll
    for (int i = 0; i < 2; ++i) {
#pragma unroll
        for (int j = 0; j < 4; ++j) {
            int o = nb + j * 8;
            float b0v = bias[o], b1v = bias[o + 1];
            int m_a = mb + i * 16;
            int m_b = m_a + 8;
            size_t pa_ = ((size_t)(b * NC + o) << 12);
            size_t pb_ = ((size_t)(b * NC + o + 1) << 12);
            g_shr[pa_ + (m_a & 4095)] = fmaxf(acc[i][j][0] + b0v, 0.f);
            g_shr[pb_ + (m_a & 4095)] = fmaxf(acc[i][j][1] + b1v, 0.f);
            g_shr[pa_ + (m_b & 4095)] = fmaxf(acc[i][j][2] + b0v, 0.f);
            g_shr[pb_ + (m_b & 4095)] = fmaxf(acc[i][j][3] + b1v, 0.f);
        }
    }
}

// ---------------- 3: 1x1 convs (cls 18 + reg 36 = 54 outputs) ----------------
__global__ void k_conv2(const float* __restrict__ cls_w, const float* __restrict__ cls_b,
                        const float* __restrict__ reg_w, const float* __restrict__ reg_b) {
    int blk = blockIdx.x;        // (b,y)
    int b = blk >> 6, y = blk & 63;
    __shared__ float sin_[64][64];
    __shared__ float sw[64][56];
    int tid = threadIdx.x;       // 512 threads
    int x = tid & 63, og = tid >> 6;
    float acc[7] = {};
    for (int c0 = 0; c0 < 512; c0 += 64) {
        for (int idx = tid; idx < 4096; idx += 512) {
            int c = idx >> 6, xx = idx & 63;
            sin_[c][xx] = g_shr[(((size_t)b * NC + c0 + c) * NH + y) * NW + xx];
        }
        for (int idx = tid; idx < 64 * 56; idx += 512) {
            int c = idx / 56, o = idx - c * 56;
            float v = 0.f;
            if (o < 18) v = cls_w[(size_t)o * 512 + c0 + c];
            else if (o < 54) v = reg_w[(size_t)(o - 18) * 512 + c0 + c];
            sw[c][o] = v;
        }
        __syncthreads();
#pragma unroll 8
        for (int c = 0; c < 64; ++c) {
            float a = sin_[c][x];
#pragma unroll
            for (int i = 0; i < 7; ++i) acc[i] += a * sw[c][og + 8 * i];
        }
        __syncthreads();
    }
    for (int i = 0; i < 7; ++i) {
        int o = og + 8 * i;
        if (o < 54) {
            float bs = (o < 18) ? cls_b[o] : reg_b[o - 18];
            g_act[((size_t)b * NHW + y * 64 + x) * 54 + o] = acc[i] + bs;
        }
    }
}

// -------- 4: gather + softmax + decode + clip + minsize (+anchor out) --------
__global__ void k_decode(float* __restrict__ out) {
    int K = g_K;
    int t = blockIdx.x * blockDim.x + threadIdx.x;
    if (t >= 2 * NA) {
        int i = t - 2 * NA;
        if (i < NA * 4) out[(size_t)K * 12 + 3000 + i] = g_anc[i];
        return;
    }
    if (t >= 2 * K) return;
    int b = t / K, k = t - b * K;
    int a = g_val[k];
    int pos = a / 9, j = a - pos * 9;
    const float* ab = g_act + ((size_t)b * NHW + pos) * 54;
    float l0 = ab[2 * j], l1 = ab[2 * j + 1];
    float m = fmaxf(l0, l1);
    float e0 = expf(__fadd_rn(l0, -m)), e1 = expf(__fadd_rn(l1, -m));
    float s = __fadd_rn(e0, e1);
    float p0 = __fdiv_rn(e0, s), p1 = __fdiv_rn(e1, s);
    out[(size_t)(b * K + k) * 2 + 0] = p0;
    out[(size_t)(b * K + k) * 2 + 1] = p1;
    float d0 = ab[18 + 4 * j], d1 = ab[19 + 4 * j], d2 = ab[20 + 4 * j], d3 = ab[21 + 4 * j];
    size_t ro = (size_t)4 * K;
    out[ro + (size_t)(b * K + k) * 4 + 0] = d0;
    out[ro + (size_t)(b * K + k) * 4 + 1] = d1;
    out[ro + (size_t)(b * K + k) * 4 + 2] = d2;
    out[ro + (size_t)(b * K + k) * 4 + 3] = d3;
    float ay1 = g_anc[a * 4 + 0], ax1 = g_anc[a * 4 + 1];
    float ay2 = g_anc[a * 4 + 2], ax2 = g_anc[a * 4 + 3];
    float h  = __fadd_rn(ay2, -ay1);
    float w  = __fadd_rn(ax2, -ax1);
    float cy = __fadd_rn(ay1, __fmul_rn(0.5f, h));
    float cx = __fadd_rn(ax1, __fmul_rn(0.5f, w));
    float ncy = __fadd_rn(__fmul_rn(d0, h), cy);
    float ncx = __fadd_rn(__fmul_rn(d1, w), cx);
    float nh = __fmul_rn(h, expf(d2));
    float nw = __fmul_rn(w, expf(d3));
    float y1 = __fadd_rn(ncy, -__fmul_rn(0.5f, nh));
    float x1 = __fadd_rn(ncx, -__fmul_rn(0.5f, nw));
    float y2 = __fadd_rn(ncy,  __fmul_rn(0.5f, nh));
    float x2 = __fadd_rn(ncx,  __fmul_rn(0.5f, nw));
    y1 = fminf(fmaxf(y1, 0.f), 1024.f);
    x1 = fminf(fmaxf(x1, 0.f), 1024.f);
    y2 = fminf(fmaxf(y2, 0.f), 1024.f);
    x2 = fminf(fmaxf(x2, 0.f), 1024.f);
    float hs = __fadd_rn(y2, -y1), ws = __fadd_rn(x2, -x1);
    float score = (hs >= 16.f && ws >= 16.f) ? p1 : -INFINITY;
    g_box[(size_t)b * NA + k] = make_float4(y1, x1, y2, x2);
    g_sco[(size_t)b * NA + k] = score;
}

// ---------------- bitonic sorts (shared, n=2048, 1024 threads) ---------------
__device__ void bitonic2048_u64(unsigned long long* buf, int tid) {
    for (int k = 2; k <= 2048; k <<= 1)
        for (int j = k >> 1; j > 0; j >>= 1) {
            for (int i = tid; i < 2048; i += 1024) {
                int ixj = i ^ j;
                if (ixj > i) {
                    unsigned long long a = buf[i], c = buf[ixj];
                    bool up = ((i & k) == 0);
                    if ((a > c) == up) { buf[i] = c; buf[ixj] = a; }
                }
            }
            __syncthreads();
        }
}
__device__ void bitonic2048_u32(unsigned* buf, int tid) {
    for (int k = 2; k <= 2048; k <<= 1)
        for (int j = k >> 1; j > 0; j >>= 1) {
            for (int i = tid; i < 2048; i += 1024) {
                int ixj = i ^ j;
                if (ixj > i) {
                    unsigned a = buf[i], c = buf[ixj];
                    bool up = ((i & k) == 0);
                    if ((a > c) == up) { buf[i] = c; buf[ixj] = a; }
                }
            }
            __syncthreads();
        }
}

// ---------------- 6: exact top-2000 (radix select + sort), per batch ---------
__global__ void k_topk() {
    int b = blockIdx.x;
    int tid = threadIdx.x;                 // 1024
    int N = g_K;
    const float* sc = g_sco + (size_t)b * NA;
    __shared__ unsigned hist[256];
    __shared__ unsigned long long sbuf[2048];
    __shared__ unsigned idxbuf[2048];
    __shared__ int s_bin, s_need, s_cgt, s_ceq;

    unsigned prefix = 0;
    int need = PRE;
    for (int shift = 24; shift >= 0; shift -= 8) {
        if (tid < 256) hist[tid] = 0;
        __syncthreads();
        unsigned himask = (shift == 24) ? 0u : (0xFFFFFFFFu << (shift + 8));
        for (int i = tid; i < N; i += 1024) {
            unsigned key = fkey(sc[i]);
            if ((key & himask) == prefix) atomicAdd(&hist[(key >> shift) & 255u], 1u);
        }
        __syncthreads();
        if (tid == 0) {
            int nd = need, bin = 255;
            for (; bin >= 0; --bin) {
                int c = (int)hist[bin];
                if (nd <= c) break;
                nd -= c;
            }
            s_bin = bin; s_need = nd;
        }
        __syncthreads();
        prefix |= ((unsigned)s_bin) << shift;
        need = s_need;
        __syncthreads();
    }
    unsigned T = prefix;

    if (tid == 0) { s_cgt = 0; s_ceq = 0; }
    for (int i = tid; i < 2048; i += 1024) { sbuf[i] = ~0ULL; idxbuf[i] = 0xFFFFFFFFu; }
    __syncthreads();
    for (int i = tid; i < N; i += 1024) {
        unsigned key = fkey(sc[i]);
        if (key > T) {
            int p = atomicAdd(&s_cgt, 1);
            sbuf[p] = (((unsigned long long)(~key)) << 32) | (unsigned)i;
        } else if (key == T) {
            int p = atomicAdd(&s_ceq, 1);
            if (p < 2048) idxbuf[p] = (unsigned)i;
        }
    }
    __syncthreads();
    bitonic2048_u32(idxbuf, tid);
    int cgt = s_cgt;
    for (int t2 = tid; t2 < need; t2 += 1024)
        sbuf[cgt + t2] = (((unsigned long long)(~T)) << 32) | idxbuf[t2];
    __syncthreads();
    bitonic2048_u64(sbuf, tid);
    for (int t2 = tid; t2 < PRE; t2 += 1024) {
        unsigned idx = (unsigned)(sbuf[t2] & 0xFFFFFFFFu);
        g_tb[b * PRE + t2] = g_box[(size_t)b * NA + idx];
        g_ts[b * PRE + t2] = sc[idx];
    }
}

// ---------------- 7a: parallel IoU suppression bitmask -----------------------
__global__ void k_iou() {
    __shared__ float4 jb[64];
    __shared__ float ja[64];
    int b = blockIdx.z;
    int ti = threadIdx.x;      // 64
    int j0 = blockIdx.y * 64;
    float4 bb = make_float4(0.f, 0.f, 0.f, 0.f);
    if (j0 + ti < PRE) bb = g_tb[b * PRE + j0 + ti];
    jb[ti] = bb;
    ja[ti] = __fmul_rn(__fadd_rn(bb.z, -bb.x), __fadd_rn(bb.w, -bb.y));
    __syncthreads();
    int i = blockIdx.x * 64 + ti;
    if (i >= PRE) return;
    float4 bi = g_tb[b * PRE + i];
    float ai = __fmul_rn(__fadd_rn(bi.z, -bi.x), __fadd_rn(bi.w, -bi.y));
    unsigned w0 = 0, w1 = 0;
#pragma unroll
    for (int jj = 0; jj < 64; ++jj) {
        float4 bj = jb[jj];
        float yy1 = fmaxf(bi.x, bj.x), xx1 = fmaxf(bi.y, bj.y);
        float yy2 = fminf(bi.z, bj.z), xx2 = fminf(bi.w, bj.w);
        float inter = __fmul_rn(fmaxf(__fadd_rn(yy2, -yy1), 0.f),
                                fmaxf(__fadd_rn(xx2, -xx1), 0.f));
        float denom = __fadd_rn(__fadd_rn(__fadd_rn(ai, ja[jj]), -inter), 1e-9f);
        if (__fdiv_rn(inter, denom) > 0.7f) {
            if (jj < 32) w0 |= 1u << jj; else w1 |= 1u << (jj - 32);
        }
    }
    size_t mb = ((size_t)b * PRE + i) * 64 + blockIdx.y * 2;
    g_mask[mb] = w0;
    g_mask[mb + 1] = w1;
}

// ---------------- 7b: single-warp bitset greedy scan -------------------------
__global__ void k_nms_scan(float* __restrict__ out) {
    int b = blockIdx.x;
    int lane = threadIdx.x;    // 32
    int K = g_K;
    size_t OFF_ROI = (size_t)K * 12;
    size_t OFF_ID  = OFF_ROI + 2400;
    __shared__ unsigned supp[63], valid[63];
    for (int w = lane; w < 63; w += 32) {
        unsigned v = 0;
        for (int bit = 0; bit < 32; ++bit) {
            int i = w * 32 + bit;
            if (i < PRE && g_ts[b * PRE + i] > -INFINITY) v |= 1u << bit;
        }
        valid[w] = v;
        supp[w] = 0;
    }
    __syncwarp();
    int kept = 0;
    for (int w = 0; w < 63 && kept < POST; ++w) {
        while (kept < POST) {
            unsigned live = valid[w] & ~supp[w];
            if (!live) break;
            int bit = __ffs(live) - 1;
            int i = w * 32 + bit;
            if (lane == 0) {
                float4 bbx = g_tb[b * PRE + i];
                float* ro = out + OFF_ROI + ((size_t)b * POST + kept) * 4;
                ro[0] = bbx.x; ro[1] = bbx.y; ro[2] = bbx.z; ro[3] = bbx.w;
            }
            kept++;
            const unsigned* mrow = &g_mask[((size_t)b * PRE + i) * 64];
            unsigned ex0 = (lane == w) ? (1u << bit) : 0u;
            supp[lane] |= mrow[lane] | ex0;
            int w2 = lane + 32;
            if (w2 < 63) {
                unsigned ex1 = (w2 == w) ? (1u << bit) : 0u;
                supp[w2] |= mrow[w2] | ex1;
            }
            __syncwarp();
        }
    }
    for (int i = lane; i < POST; i += 32) {
        if (i >= kept) {
            float* ro = out + OFF_ROI + ((size_t)b * POST + i) * 4;
            ro[0] = 0.f; ro[1] = 0.f; ro[2] = 0.f; ro[3] = 0.f;
        }
        out[OFF_ID + b * POST + i] = (float)b;
    }
}

// ---------------- launch ----------------
extern "C" void kernel_launch(void* const* d_in, const int* in_sizes, int n_in,
                              void* d_out, int out_size) {
    const float* feat    = (const float*)d_in[0];
    const float* share_w = (const float*)d_in[1];
    const float* share_b = (const float*)d_in[2];
    const float* cls_w   = (const float*)d_in[3];
    const float* cls_b   = (const float*)d_in[4];
    const float* reg_w   = (const float*)d_in[5];
    const float* reg_b   = (const float*)d_in[6];
    float* out = (float*)d_out;

    cudaFuncSetAttribute(k_conv1mma, cudaFuncAttributeMaxDynamicSharedMemorySize, SMEM_CONV);

    k_prep<<<WSP_BLKS + FSP_BLKS + HALO_BLKS, 256>>>(share_w, feat);
    k_anchors<<<1, 1024>>>();
    k_conv1mma<<<dim3(64, 8), 256, SMEM_CONV>>>(share_b);
    k_conv2<<<128, 512>>>(cls_w, cls_b, reg_w, reg_b);
    k_decode<<<(6 * NA + 255) / 256, 256>>>(out);
    k_topk<<<2, 1024>>>();
    k_iou<<<dim3(32, 32, 2), 64>>>();
    k_nms_scan<<<2, 32>>>(out);
}